// round 5
// baseline (speedup 1.0000x reference)
#include <cuda_runtime.h>
#include <cuda_bf16.h>
#include <cstdint>

// Problem constants
#define S_LEN 2048
#define BATCH 2
#define EMBED 1024
#define HEADS 16
#define HDIM  64
#define M_ROWS (S_LEN * BATCH)        // 4096
#define QKV_COLS (3 * EMBED)          // 3072

// Q scale folded with log2(e) so softmax can use exp2 directly
#define QSCALE 0.18033688011112042f   // 0.125 * log2(e)

// ---------------------------------------------------------------------------
// Scratch (device globals; no allocation in kernel_launch)
// ---------------------------------------------------------------------------
__device__ __align__(16) __nv_bfloat16 g_xhi[(size_t)M_ROWS * EMBED];
__device__ __align__(16) __nv_bfloat16 g_xlo[(size_t)M_ROWS * EMBED];
__device__ __align__(16) __nv_bfloat16 g_w1hi[(size_t)QKV_COLS * EMBED];
__device__ __align__(16) __nv_bfloat16 g_w1lo[(size_t)QKV_COLS * EMBED];
__device__ __align__(16) __nv_bfloat16 g_w2hi[(size_t)EMBED * EMBED];
__device__ __align__(16) __nv_bfloat16 g_w2lo[(size_t)EMBED * EMBED];
__device__ __align__(16) __nv_bfloat16 g_qkvhi[(size_t)M_ROWS * QKV_COLS];
__device__ __align__(16) __nv_bfloat16 g_qkvlo[(size_t)M_ROWS * QKV_COLS];
__device__ __align__(16) __nv_bfloat16 g_ahi[(size_t)M_ROWS * EMBED];
__device__ __align__(16) __nv_bfloat16 g_alo[(size_t)M_ROWS * EMBED];

// ---------------------------------------------------------------------------
// PTX helpers (baseline compute_103-safe: mma.sync + ldmatrix + cp.async)
// ---------------------------------------------------------------------------
__device__ __forceinline__ uint32_t smem_u32(const void* p) {
    uint32_t addr;
    asm("{ .reg .u64 t; cvta.to.shared.u64 t, %1; cvt.u32.u64 %0, t; }"
        : "=r"(addr) : "l"(p));
    return addr;
}

__device__ __forceinline__ void cp16(uint32_t dst, const void* src) {
    asm volatile("cp.async.cg.shared.global [%0], [%1], 16;" :: "r"(dst), "l"(src));
}
#define CP_COMMIT() asm volatile("cp.async.commit_group;" ::: "memory")
#define CP_WAIT1()  asm volatile("cp.async.wait_group 1;" ::: "memory")

#define LDSM_X4(r0, r1, r2, r3, addr) \
    asm volatile("ldmatrix.sync.aligned.m8n8.x4.shared.b16 {%0,%1,%2,%3}, [%4];" \
        : "=r"(r0), "=r"(r1), "=r"(r2), "=r"(r3) : "r"(addr))

#define LDSM_X4_T(r0, r1, r2, r3, addr) \
    asm volatile("ldmatrix.sync.aligned.m8n8.x4.trans.shared.b16 {%0,%1,%2,%3}, [%4];" \
        : "=r"(r0), "=r"(r1), "=r"(r2), "=r"(r3) : "r"(addr))

__device__ __forceinline__ void mma16816(float* c, const uint32_t* a,
                                         const uint32_t b0, const uint32_t b1) {
    asm volatile(
        "mma.sync.aligned.m16n8k16.row.col.f32.bf16.bf16.f32 "
        "{%0,%1,%2,%3}, {%4,%5,%6,%7}, {%8,%9}, {%0,%1,%2,%3};"
        : "+f"(c[0]), "+f"(c[1]), "+f"(c[2]), "+f"(c[3])
        : "r"(a[0]), "r"(a[1]), "r"(a[2]), "r"(a[3]), "r"(b0), "r"(b1));
}

__device__ __forceinline__ void pack_split(float f0, float f1,
                                           uint32_t& hi, uint32_t& lo) {
    __nv_bfloat162 h = __floats2bfloat162_rn(f0, f1);
    float2 hf = __bfloat1622float2(h);
    __nv_bfloat162 l = __floats2bfloat162_rn(f0 - hf.x, f1 - hf.y);
    hi = *reinterpret_cast<uint32_t*>(&h);
    lo = *reinterpret_cast<uint32_t*>(&l);
}

__device__ __forceinline__ void split2_store(float v0, float v1,
                                             __nv_bfloat16* hip,
                                             __nv_bfloat16* lop) {
    __nv_bfloat162 h = __floats2bfloat162_rn(v0, v1);
    float2 hf = __bfloat1622float2(h);
    __nv_bfloat162 l = __floats2bfloat162_rn(v0 - hf.x, v1 - hf.y);
    *reinterpret_cast<__nv_bfloat162*>(hip) = h;
    *reinterpret_cast<__nv_bfloat162*>(lop) = l;
}

// ---------------------------------------------------------------------------
// fp32 -> bf16 hi/lo split (vectorized by 4)
// ---------------------------------------------------------------------------
__global__ __launch_bounds__(256) void split_bf16_kernel(
    const float4* __restrict__ in, ushort4* __restrict__ hi,
    ushort4* __restrict__ lo)
{
    int i = blockIdx.x * blockDim.x + threadIdx.x;
    float4 v = in[i];
    __nv_bfloat16 h0 = __float2bfloat16(v.x);
    __nv_bfloat16 h1 = __float2bfloat16(v.y);
    __nv_bfloat16 h2 = __float2bfloat16(v.z);
    __nv_bfloat16 h3 = __float2bfloat16(v.w);
    __nv_bfloat16 l0 = __float2bfloat16(v.x - __bfloat162float(h0));
    __nv_bfloat16 l1 = __float2bfloat16(v.y - __bfloat162float(h1));
    __nv_bfloat16 l2 = __float2bfloat16(v.z - __bfloat162float(h2));
    __nv_bfloat16 l3 = __float2bfloat16(v.w - __bfloat162float(h3));
    hi[i] = make_ushort4(__bfloat16_as_ushort(h0), __bfloat16_as_ushort(h1),
                         __bfloat16_as_ushort(h2), __bfloat16_as_ushort(h3));
    lo[i] = make_ushort4(__bfloat16_as_ushort(l0), __bfloat16_as_ushort(l1),
                         __bfloat16_as_ushort(l2), __bfloat16_as_ushort(l3));
}

// ---------------------------------------------------------------------------
// mma.sync GEMM:  C = Ahi*Whi^T + Ahi*Wlo^T + Alo*Whi^T + bias
// CTA tile 128x256, 8 warps (2 M x 4 N), warp tile 64x64.
// K staged 64 elems (128B rows, XOR swizzle), double-buffered cp.async.
// grid = (Ntot/256, M/128), 256 threads.
// Columns < qcols are scaled by QSCALE in the epilogue.
// ---------------------------------------------------------------------------
#define GK 1024
#define KSTEP 64
#define NSTAGE (GK / KSTEP)          // 16
#define STAGE_BYTES 98304            // A hi/lo 2x16KB + W hi/lo 2x32KB
#define GEMM_SMEM (2 * STAGE_BYTES)  // 196608

__global__ __launch_bounds__(256, 1) void gemm_mma_kernel(
    const __nv_bfloat16* __restrict__ Ahi, const __nv_bfloat16* __restrict__ Alo,
    const __nv_bfloat16* __restrict__ Whi, const __nv_bfloat16* __restrict__ Wlo,
    const float* __restrict__ bias, float* __restrict__ Cf,
    __nv_bfloat16* __restrict__ Chi, __nv_bfloat16* __restrict__ Clo,
    int Ntot, int qcols)
{
    extern __shared__ char sm_raw[];
    const uint32_t smem_base = smem_u32(sm_raw);
    const int tid = threadIdx.x;
    const int wid = tid >> 5;
    const int lane = tid & 31;
    const int warpM = wid & 1;
    const int warpN = wid >> 1;
    const int rowBase = blockIdx.y * 128;
    const int colBase = blockIdx.x * 256;

    // stage layout: Ahi 0, Alo 16384, Whi 32768, Wlo 65536
    auto load_stage = [&](int s, int buf) {
        const int k0 = s * KSTEP;
        const uint32_t base = smem_base + (uint32_t)buf * STAGE_BYTES;
#pragma unroll
        for (int i = 0; i < 24; i++) {
            int idx = tid + (i << 8);           // 0..6143
            if (idx < 2048) {
                int mat = idx >> 10;            // 0:Ahi 1:Alo
                int r = (idx >> 3) & 127;
                int c16 = idx & 7;
                const __nv_bfloat16* srcb = mat ? Alo : Ahi;
                const void* src = srcb + (size_t)(rowBase + r) * GK + k0 + c16 * 8;
                uint32_t dst = base + (uint32_t)(mat * 16384 + r * 128 +
                                                 ((c16 ^ (r & 7)) * 16));
                cp16(dst, src);
            } else {
                int idx2 = idx - 2048;          // 0..4095
                int mat = idx2 >> 11;           // 0:Whi 1:Wlo
                int r = (idx2 >> 3) & 255;
                int c16 = idx2 & 7;
                const __nv_bfloat16* srcb = mat ? Wlo : Whi;
                const void* src = srcb + (size_t)(colBase + r) * GK + k0 + c16 * 8;
                uint32_t dst = base + 32768u + (uint32_t)(mat * 32768 + r * 128 +
                                                          ((c16 ^ (r & 7)) * 16));
                cp16(dst, src);
            }
        }
    };

    float acc[4][8][4];
#pragma unroll
    for (int mi = 0; mi < 4; mi++)
#pragma unroll
        for (int ni = 0; ni < 8; ni++)
#pragma unroll
            for (int j = 0; j < 4; j++) acc[mi][ni][j] = 0.f;

    const int aRow = warpM * 64 + (lane & 15);
    const int aHalf = lane >> 4;
    const int bRow = warpN * 64 + ((lane >> 4) * 8) + (lane & 7);
    const int bHalf = (lane >> 3) & 1;

    load_stage(0, 0);
    CP_COMMIT();

    for (int s = 0; s < NSTAGE; s++) {
        const int buf = s & 1;
        if (s + 1 < NSTAGE) load_stage(s + 1, buf ^ 1);
        CP_COMMIT();
        CP_WAIT1();
        __syncthreads();

        const uint32_t base = smem_base + (uint32_t)buf * STAGE_BYTES;
#pragma unroll
        for (int kk = 0; kk < 4; kk++) {
            uint32_t ah[4][4], al[4][4], bh[4][4], bl[4][4];
#pragma unroll
            for (int mi = 0; mi < 4; mi++) {
                int r = aRow + mi * 16;
                int c16 = kk * 2 + aHalf;
                uint32_t off = (uint32_t)(r * 128 + ((c16 ^ (r & 7)) * 16));
                LDSM_X4(ah[mi][0], ah[mi][1], ah[mi][2], ah[mi][3], base + off);
                LDSM_X4(al[mi][0], al[mi][1], al[mi][2], al[mi][3],
                        base + 16384u + off);
            }
#pragma unroll
            for (int np = 0; np < 4; np++) {
                int r = bRow + np * 16;
                int c16 = kk * 2 + bHalf;
                uint32_t off = (uint32_t)(r * 128 + ((c16 ^ (r & 7)) * 16));
                LDSM_X4(bh[np][0], bh[np][1], bh[np][2], bh[np][3],
                        base + 32768u + off);
                LDSM_X4(bl[np][0], bl[np][1], bl[np][2], bl[np][3],
                        base + 65536u + off);
            }
#pragma unroll
            for (int mi = 0; mi < 4; mi++)
#pragma unroll
                for (int ni = 0; ni < 8; ni++) {
                    const int np = ni >> 1, sub = (ni & 1) * 2;
                    mma16816(acc[mi][ni], ah[mi], bh[np][sub], bh[np][sub + 1]);
                    mma16816(acc[mi][ni], ah[mi], bl[np][sub], bl[np][sub + 1]);
                    mma16816(acc[mi][ni], al[mi], bh[np][sub], bh[np][sub + 1]);
                }
        }
        __syncthreads();
    }

    const int erow = rowBase + warpM * 64 + (lane >> 2);
    const int ecol0 = colBase + warpN * 64 + (lane & 3) * 2;
#pragma unroll
    for (int ni = 0; ni < 8; ni++) {
        const int col = ecol0 + ni * 8;
        const float sc = (col < qcols) ? QSCALE : 1.f;
        const float bx = bias[col], by = bias[col + 1];
#pragma unroll
        for (int mi = 0; mi < 4; mi++) {
            const int r0 = erow + mi * 16;
            float v0 = (acc[mi][ni][0] + bx) * sc;
            float v1 = (acc[mi][ni][1] + by) * sc;
            float v2 = (acc[mi][ni][2] + bx) * sc;
            float v3 = (acc[mi][ni][3] + by) * sc;
            if (Cf) {
                *(float2*)&Cf[(size_t)r0 * Ntot + col] = make_float2(v0, v1);
                *(float2*)&Cf[(size_t)(r0 + 8) * Ntot + col] = make_float2(v2, v3);
            } else {
                split2_store(v0, v1, Chi + (size_t)r0 * Ntot + col,
                             Clo + (size_t)r0 * Ntot + col);
                split2_store(v2, v3, Chi + (size_t)(r0 + 8) * Ntot + col,
                             Clo + (size_t)(r0 + 8) * Ntot + col);
            }
        }
    }
}

// ---------------------------------------------------------------------------
// Flash attention on mma.sync bf16 (hi/lo split, exp2-domain softmax).
// grid (S/128, B*H), 256 threads (8 warps x 16 q rows each).
// KV chunk = 128 rows, double buffered.
// smem: Qhi 0, Qlo 16384; per buf (65536): KH 0, KL 16384, VH 32768, VL 49152.
// ---------------------------------------------------------------------------
#define FL_SMEM 163840
#define FCHUNK 128
#define NCHUNK (S_LEN / FCHUNK)   // 16

__global__ __launch_bounds__(256, 1) void flash_mma_kernel(
    const __nv_bfloat16* __restrict__ qh, const __nv_bfloat16* __restrict__ ql,
    __nv_bfloat16* __restrict__ ohi, __nv_bfloat16* __restrict__ olo)
{
    extern __shared__ char sm_raw[];
    const uint32_t sb = smem_u32(sm_raw);
    const int tid = threadIdx.x;
    const int wid = tid >> 5;
    const int lane = tid & 31;
    const int q0 = blockIdx.x * 128;
    const int b = blockIdx.y >> 4;
    const int h = blockIdx.y & 15;
    const int qcol = h * HDIM;
    const int kcol = EMBED + h * HDIM;
    const int vcol = 2 * EMBED + h * HDIM;

    // ---- load Q tile (hi+lo): 2048 cp16 ----
#pragma unroll
    for (int i = 0; i < 8; i++) {
        int idx = tid + (i << 8);
        int mat = idx >> 10;
        int r = (idx >> 3) & 127;
        int c16 = idx & 7;
        const __nv_bfloat16* sp = mat ? ql : qh;
        const void* src = sp + (size_t)((q0 + r) * 2 + b) * QKV_COLS + qcol + c16 * 8;
        uint32_t dst = sb + (uint32_t)(mat * 16384 + r * 128 +
                                       ((c16 ^ (r & 7)) * 16));
        cp16(dst, src);
    }
    CP_COMMIT();

    auto load_kv = [&](int j0, int buf) {
        const uint32_t base = sb + 32768u + (uint32_t)buf * 65536u;
#pragma unroll
        for (int i = 0; i < 16; i++) {
            int idx = tid + (i << 8);       // 0..4095
            int mat = idx >> 10;            // 0:KH 1:KL 2:VH 3:VL
            int r = (idx >> 3) & 127;
            int c16 = idx & 7;
            const __nv_bfloat16* sp = (mat & 1) ? ql : qh;
            int colb = (mat >> 1) ? vcol : kcol;
            const void* src = sp + (size_t)((j0 + r) * 2 + b) * QKV_COLS + colb + c16 * 8;
            uint32_t dst = base + (uint32_t)(mat * 16384 + r * 128 +
                                             ((c16 ^ (r & 7)) * 16));
            cp16(dst, src);
        }
    };

    load_kv(0, 0);
    CP_COMMIT();
    CP_WAIT1();      // Q resident (chunk0 may still be in flight)
    __syncthreads();

    // ---- Q fragments into registers ----
    uint32_t aqh[4][4], aql[4][4];
    {
        int r = wid * 16 + (lane & 15);
#pragma unroll
        for (int kk = 0; kk < 4; kk++) {
            int c16 = kk * 2 + (lane >> 4);
            uint32_t off = (uint32_t)(r * 128 + ((c16 ^ (r & 7)) * 16));
            LDSM_X4(aqh[kk][0], aqh[kk][1], aqh[kk][2], aqh[kk][3], sb + off);
            LDSM_X4(aql[kk][0], aql[kk][1], aql[kk][2], aql[kk][3],
                    sb + 16384u + off);
        }
    }

    float O[8][4];
#pragma unroll
    for (int ni = 0; ni < 8; ni++)
#pragma unroll
        for (int j = 0; j < 4; j++) O[ni][j] = 0.f;
    float m0 = -1e30f, m1 = -1e30f, l0 = 0.f, l1 = 0.f;

    for (int s = 0; s < NCHUNK; s++) {
        if (s + 1 < NCHUNK) load_kv((s + 1) * FCHUNK, (s + 1) & 1);
        CP_COMMIT();
        CP_WAIT1();
        __syncthreads();

        const uint32_t kb = sb + 32768u + (uint32_t)(s & 1) * 65536u;

        // ---- QK^T: scores for 128 kv cols ----
        float sc[16][4];
#pragma unroll
        for (int ni = 0; ni < 16; ni++)
#pragma unroll
            for (int j = 0; j < 4; j++) sc[ni][j] = 0.f;

        {
            const int rb = ((lane >> 4) * 8) + (lane & 7);
#pragma unroll
            for (int kk = 0; kk < 4; kk++) {
                const int c16 = kk * 2 + ((lane >> 3) & 1);
#pragma unroll
                for (int np = 0; np < 8; np++) {
                    int r = rb + np * 16;
                    uint32_t off = (uint32_t)(r * 128 + ((c16 ^ (r & 7)) * 16));
                    uint32_t kh[4], kl[4];
                    LDSM_X4(kh[0], kh[1], kh[2], kh[3], kb + off);
                    LDSM_X4(kl[0], kl[1], kl[2], kl[3], kb + 16384u + off);
                    float* s0 = sc[np * 2];
                    float* s1 = sc[np * 2 + 1];
                    mma16816(s0, aqh[kk], kh[0], kh[1]);
                    mma16816(s0, aqh[kk], kl[0], kl[1]);
                    mma16816(s0, aql[kk], kh[0], kh[1]);
                    mma16816(s1, aqh[kk], kh[2], kh[3]);
                    mma16816(s1, aqh[kk], kl[2], kl[3]);
                    mma16816(s1, aql[kk], kh[2], kh[3]);
                }
            }
        }

        // ---- online softmax (exp2 domain; two row-halves per thread) ----
#pragma unroll
        for (int hh = 0; hh < 2; hh++) {
            const int j0 = hh * 2, j1 = hh * 2 + 1;
            float& m = hh ? m1 : m0;
            float& l = hh ? l1 : l0;
            float mx = -1e30f;
#pragma unroll
            for (int ni = 0; ni < 16; ni++)
                mx = fmaxf(mx, fmaxf(sc[ni][j0], sc[ni][j1]));
            mx = fmaxf(mx, __shfl_xor_sync(0xffffffffu, mx, 1));
            mx = fmaxf(mx, __shfl_xor_sync(0xffffffffu, mx, 2));
            float mn = fmaxf(m, mx);
            float alpha = exp2f(m - mn);
            m = mn;
            float sum = 0.f;
#pragma unroll
            for (int ni = 0; ni < 16; ni++) {
                sc[ni][j0] = exp2f(sc[ni][j0] - mn);
                sc[ni][j1] = exp2f(sc[ni][j1] - mn);
                sum += sc[ni][j0] + sc[ni][j1];
            }
            sum += __shfl_xor_sync(0xffffffffu, sum, 1);
            sum += __shfl_xor_sync(0xffffffffu, sum, 2);
            l = l * alpha + sum;
#pragma unroll
            for (int ni = 0; ni < 8; ni++) {
                O[ni][j0] *= alpha;
                O[ni][j1] *= alpha;
            }
        }

        // ---- P @ V over the 128-row chunk ----
#pragma unroll
        for (int kk2 = 0; kk2 < 8; kk2++) {
            uint32_t ph[4], pl[4];
            pack_split(sc[2 * kk2][0],     sc[2 * kk2][1],     ph[0], pl[0]);
            pack_split(sc[2 * kk2][2],     sc[2 * kk2][3],     ph[1], pl[1]);
            pack_split(sc[2 * kk2 + 1][0], sc[2 * kk2 + 1][1], ph[2], pl[2]);
            pack_split(sc[2 * kk2 + 1][2], sc[2 * kk2 + 1][3], ph[3], pl[3]);

            uint32_t vh[4][4], vl[4][4];
            const int g = lane >> 3;
            const int row = kk2 * 16 + (g & 1) * 8 + (lane & 7);
#pragma unroll
            for (int g4 = 0; g4 < 4; g4++) {
                int c16 = g4 * 2 + (g >> 1);
                uint32_t off = (uint32_t)(row * 128 + ((c16 ^ (row & 7)) * 16));
                LDSM_X4_T(vh[g4][0], vh[g4][1], vh[g4][2], vh[g4][3],
                          kb + 32768u + off);
                LDSM_X4_T(vl[g4][0], vl[g4][1], vl[g4][2], vl[g4][3],
                          kb + 49152u + off);
            }
#pragma unroll
            for (int ni = 0; ni < 8; ni++) {
                const int g4 = ni >> 1, sub = (ni & 1) * 2;
                mma16816(O[ni], ph, vh[g4][sub], vh[g4][sub + 1]);
                mma16816(O[ni], ph, vl[g4][sub], vl[g4][sub + 1]);
                mma16816(O[ni], pl, vh[g4][sub], vh[g4][sub + 1]);
            }
        }
        __syncthreads();
    }

    // ---- epilogue: normalize, split hi/lo, store ----
    const float inv0 = 1.f / l0;
    const float inv1 = 1.f / l1;
    const int sA = q0 + wid * 16 + (lane >> 2);
    const size_t rowA = (size_t)(sA * 2 + b) * EMBED;
    const size_t rowB = (size_t)((sA + 8) * 2 + b) * EMBED;
    const int colb = h * HDIM + (lane & 3) * 2;
#pragma unroll
    for (int ni = 0; ni < 8; ni++) {
        const int col = colb + ni * 8;
        split2_store(O[ni][0] * inv0, O[ni][1] * inv0,
                     ohi + rowA + col, olo + rowA + col);
        split2_store(O[ni][2] * inv1, O[ni][3] * inv1,
                     ohi + rowB + col, olo + rowB + col);
    }
}

// ---------------------------------------------------------------------------
extern "C" void kernel_launch(void* const* d_in, const int* in_sizes, int n_in,
                              void* d_out, int out_size)
{
    (void)in_sizes; (void)n_in; (void)out_size;
    const float* x    = (const float*)d_in[0];
    const float* Win  = (const float*)d_in[1];
    const float* bin  = (const float*)d_in[2];
    const float* Wout = (const float*)d_in[3];
    const float* bout = (const float*)d_in[4];
    float* out = (float*)d_out;

    __nv_bfloat16 *xhi, *xlo, *w1hi, *w1lo, *w2hi, *w2lo;
    __nv_bfloat16 *qkvhi, *qkvlo, *ahi, *alo;
    cudaGetSymbolAddress((void**)&xhi, g_xhi);
    cudaGetSymbolAddress((void**)&xlo, g_xlo);
    cudaGetSymbolAddress((void**)&w1hi, g_w1hi);
    cudaGetSymbolAddress((void**)&w1lo, g_w1lo);
    cudaGetSymbolAddress((void**)&w2hi, g_w2hi);
    cudaGetSymbolAddress((void**)&w2lo, g_w2lo);
    cudaGetSymbolAddress((void**)&qkvhi, g_qkvhi);
    cudaGetSymbolAddress((void**)&qkvlo, g_qkvlo);
    cudaGetSymbolAddress((void**)&ahi, g_ahi);
    cudaGetSymbolAddress((void**)&alo, g_alo);

    cudaFuncSetAttribute(gemm_mma_kernel,
                         cudaFuncAttributeMaxDynamicSharedMemorySize, GEMM_SMEM);
    cudaFuncSetAttribute(flash_mma_kernel,
                         cudaFuncAttributeMaxDynamicSharedMemorySize, FL_SMEM);

    // 0) fp32 -> bf16 hi/lo splits for inputs
    split_bf16_kernel<<<(M_ROWS * EMBED) / 1024, 256>>>(
        (const float4*)x, (ushort4*)xhi, (ushort4*)xlo);
    split_bf16_kernel<<<(QKV_COLS * EMBED) / 1024, 256>>>(
        (const float4*)Win, (ushort4*)w1hi, (ushort4*)w1lo);
    split_bf16_kernel<<<(EMBED * EMBED) / 1024, 256>>>(
        (const float4*)Wout, (ushort4*)w2hi, (ushort4*)w2lo);

    // 1) QKV projection -> bf16 hi/lo qkv (Q pre-scaled by 0.125*log2e)
    gemm_mma_kernel<<<dim3(QKV_COLS / 256, M_ROWS / 128), 256, GEMM_SMEM>>>(
        xhi, xlo, w1hi, w1lo, bin, nullptr, qkvhi, qkvlo, QKV_COLS, EMBED);

    // 2) Flash attention on tensor cores -> bf16 hi/lo attn
    flash_mma_kernel<<<dim3(S_LEN / 128, BATCH * HEADS), 256, FL_SMEM>>>(
        qkvhi, qkvlo, ahi, alo);

    // 3) Output projection -> fp32 out
    gemm_mma_kernel<<<dim3(EMBED / 256, M_ROWS / 128), 256, GEMM_SMEM>>>(
        ahi, alo, w2hi, w2lo, bout, out, nullptr, nullptr, EMBED, 0);
}

// round 6
// speedup vs baseline: 1.4238x; 1.4238x over previous
#include <cuda_runtime.h>
#include <cuda_bf16.h>
#include <cstdint>

// Problem constants
#define S_LEN 2048
#define BATCH 2
#define EMBED 1024
#define HEADS 16
#define HDIM  64
#define M_ROWS (S_LEN * BATCH)        // 4096
#define QKV_COLS (3 * EMBED)          // 3072

// Q scale folded with log2(e) so softmax can use exp2 directly
#define QSCALE 0.18033688011112042f   // 0.125 * log2(e)

// ---------------------------------------------------------------------------
// Scratch (device globals; no allocation in kernel_launch)
// ---------------------------------------------------------------------------
__device__ __align__(16) __nv_bfloat16 g_xhi[(size_t)M_ROWS * EMBED];
__device__ __align__(16) __nv_bfloat16 g_xlo[(size_t)M_ROWS * EMBED];
__device__ __align__(16) __nv_bfloat16 g_w1hi[(size_t)QKV_COLS * EMBED];
__device__ __align__(16) __nv_bfloat16 g_w1lo[(size_t)QKV_COLS * EMBED];
__device__ __align__(16) __nv_bfloat16 g_w2hi[(size_t)EMBED * EMBED];
__device__ __align__(16) __nv_bfloat16 g_w2lo[(size_t)EMBED * EMBED];
__device__ __align__(16) __nv_bfloat16 g_qkvhi[(size_t)M_ROWS * QKV_COLS];
__device__ __align__(16) __nv_bfloat16 g_qkvlo[(size_t)M_ROWS * QKV_COLS];
__device__ __align__(16) __nv_bfloat16 g_ahi[(size_t)M_ROWS * EMBED];
__device__ __align__(16) __nv_bfloat16 g_alo[(size_t)M_ROWS * EMBED];

// ---------------------------------------------------------------------------
// PTX helpers (baseline compute_103-safe: mma.sync + ldmatrix + cp.async)
// ---------------------------------------------------------------------------
__device__ __forceinline__ uint32_t smem_u32(const void* p) {
    uint32_t addr;
    asm("{ .reg .u64 t; cvta.to.shared.u64 t, %1; cvt.u32.u64 %0, t; }"
        : "=r"(addr) : "l"(p));
    return addr;
}

__device__ __forceinline__ void cp16(uint32_t dst, const void* src) {
    asm volatile("cp.async.cg.shared.global [%0], [%1], 16;" :: "r"(dst), "l"(src));
}
#define CP_COMMIT() asm volatile("cp.async.commit_group;" ::: "memory")
#define CP_WAIT1()  asm volatile("cp.async.wait_group 1;" ::: "memory")

#define LDSM_X4(r0, r1, r2, r3, addr) \
    asm volatile("ldmatrix.sync.aligned.m8n8.x4.shared.b16 {%0,%1,%2,%3}, [%4];" \
        : "=r"(r0), "=r"(r1), "=r"(r2), "=r"(r3) : "r"(addr))

#define LDSM_X4_T(r0, r1, r2, r3, addr) \
    asm volatile("ldmatrix.sync.aligned.m8n8.x4.trans.shared.b16 {%0,%1,%2,%3}, [%4];" \
        : "=r"(r0), "=r"(r1), "=r"(r2), "=r"(r3) : "r"(addr))

__device__ __forceinline__ void mma16816(float* c, const uint32_t* a,
                                         const uint32_t b0, const uint32_t b1) {
    asm volatile(
        "mma.sync.aligned.m16n8k16.row.col.f32.bf16.bf16.f32 "
        "{%0,%1,%2,%3}, {%4,%5,%6,%7}, {%8,%9}, {%0,%1,%2,%3};"
        : "+f"(c[0]), "+f"(c[1]), "+f"(c[2]), "+f"(c[3])
        : "r"(a[0]), "r"(a[1]), "r"(a[2]), "r"(a[3]), "r"(b0), "r"(b1));
}

__device__ __forceinline__ float fast_exp2(float x) {
    float y;
    asm("ex2.approx.f32 %0, %1;" : "=f"(y) : "f"(x));
    return y;
}

__device__ __forceinline__ void pack_split(float f0, float f1,
                                           uint32_t& hi, uint32_t& lo) {
    __nv_bfloat162 h = __floats2bfloat162_rn(f0, f1);
    float2 hf = __bfloat1622float2(h);
    __nv_bfloat162 l = __floats2bfloat162_rn(f0 - hf.x, f1 - hf.y);
    hi = *reinterpret_cast<uint32_t*>(&h);
    lo = *reinterpret_cast<uint32_t*>(&l);
}

__device__ __forceinline__ void split2_store(float v0, float v1,
                                             __nv_bfloat16* hip,
                                             __nv_bfloat16* lop) {
    __nv_bfloat162 h = __floats2bfloat162_rn(v0, v1);
    float2 hf = __bfloat1622float2(h);
    __nv_bfloat162 l = __floats2bfloat162_rn(v0 - hf.x, v1 - hf.y);
    *reinterpret_cast<__nv_bfloat162*>(hip) = h;
    *reinterpret_cast<__nv_bfloat162*>(lop) = l;
}

// ---------------------------------------------------------------------------
// fp32 -> bf16 hi/lo split (vectorized by 4)
// ---------------------------------------------------------------------------
__global__ __launch_bounds__(256) void split_bf16_kernel(
    const float4* __restrict__ in, ushort4* __restrict__ hi,
    ushort4* __restrict__ lo)
{
    int i = blockIdx.x * blockDim.x + threadIdx.x;
    float4 v = in[i];
    __nv_bfloat16 h0 = __float2bfloat16(v.x);
    __nv_bfloat16 h1 = __float2bfloat16(v.y);
    __nv_bfloat16 h2 = __float2bfloat16(v.z);
    __nv_bfloat16 h3 = __float2bfloat16(v.w);
    __nv_bfloat16 l0 = __float2bfloat16(v.x - __bfloat162float(h0));
    __nv_bfloat16 l1 = __float2bfloat16(v.y - __bfloat162float(h1));
    __nv_bfloat16 l2 = __float2bfloat16(v.z - __bfloat162float(h2));
    __nv_bfloat16 l3 = __float2bfloat16(v.w - __bfloat162float(h3));
    hi[i] = make_ushort4(__bfloat16_as_ushort(h0), __bfloat16_as_ushort(h1),
                         __bfloat16_as_ushort(h2), __bfloat16_as_ushort(h3));
    lo[i] = make_ushort4(__bfloat16_as_ushort(l0), __bfloat16_as_ushort(l1),
                         __bfloat16_as_ushort(l2), __bfloat16_as_ushort(l3));
}

// ---------------------------------------------------------------------------
// mma.sync GEMM:  C = Ahi*Whi^T + Ahi*Wlo^T + Alo*Whi^T + bias
// CTA tile 128x128, 16 warps (4 M x 4 N), warp tile 32x32, 512 threads.
// K staged 64 elems (128B rows, XOR swizzle), double-buffered cp.async.
// grid = (Ntot/128, M/128).  Columns < qcols scaled by QSCALE.
// ---------------------------------------------------------------------------
#define GK 1024
#define KSTEP 64
#define NSTAGE (GK / KSTEP)          // 16
#define STAGE_BYTES 65536            // 4 mats x 128 rows x 128B
#define GEMM_SMEM (2 * STAGE_BYTES)  // 131072

__global__ __launch_bounds__(512, 1) void gemm_mma_kernel(
    const __nv_bfloat16* __restrict__ Ahi, const __nv_bfloat16* __restrict__ Alo,
    const __nv_bfloat16* __restrict__ Whi, const __nv_bfloat16* __restrict__ Wlo,
    const float* __restrict__ bias, float* __restrict__ Cf,
    __nv_bfloat16* __restrict__ Chi, __nv_bfloat16* __restrict__ Clo,
    int Ntot, int qcols)
{
    extern __shared__ char sm_raw[];
    const uint32_t smem_base = smem_u32(sm_raw);
    const int tid = threadIdx.x;
    const int wid = tid >> 5;
    const int lane = tid & 31;
    const int warpM = wid & 3;          // 4 warps over M
    const int warpN = wid >> 2;         // 4 warps over N
    const int rowBase = blockIdx.y * 128;
    const int colBase = blockIdx.x * 128;

    // stage layout: Ahi 0, Alo 16384, Whi 32768, Wlo 49152
    auto load_stage = [&](int s, int buf) {
        const int k0 = s * KSTEP;
        const uint32_t base = smem_base + (uint32_t)buf * STAGE_BYTES;
#pragma unroll
        for (int i = 0; i < 8; i++) {
            int idx = tid + (i << 9);          // 0..4095
            int mat = idx >> 10;               // 0:Ahi 1:Alo 2:Whi 3:Wlo
            int r   = (idx >> 3) & 127;
            int c16 = idx & 7;
            const __nv_bfloat16* srcb =
                (mat == 0) ? Ahi : (mat == 1) ? Alo : (mat == 2) ? Whi : Wlo;
            int rowg = ((mat < 2) ? rowBase : colBase) + r;
            const void* src = srcb + (size_t)rowg * GK + k0 + c16 * 8;
            uint32_t dst = base + (uint32_t)(mat * 16384 + r * 128 +
                                             ((c16 ^ (r & 7)) * 16));
            cp16(dst, src);
        }
    };

    float acc[2][4][4];
#pragma unroll
    for (int mi = 0; mi < 2; mi++)
#pragma unroll
        for (int ni = 0; ni < 4; ni++)
#pragma unroll
            for (int j = 0; j < 4; j++) acc[mi][ni][j] = 0.f;

    const int aRow = warpM * 32 + (lane & 15);
    const int aHalf = lane >> 4;
    const int bRow = warpN * 32 + ((lane >> 4) * 8) + (lane & 7);
    const int bHalf = (lane >> 3) & 1;

    load_stage(0, 0);
    CP_COMMIT();

    for (int s = 0; s < NSTAGE; s++) {
        const int buf = s & 1;
        if (s + 1 < NSTAGE) load_stage(s + 1, buf ^ 1);
        CP_COMMIT();
        CP_WAIT1();
        __syncthreads();

        const uint32_t base = smem_base + (uint32_t)buf * STAGE_BYTES;
#pragma unroll
        for (int kk = 0; kk < 4; kk++) {
            uint32_t ah[2][4], al[2][4], bh[2][4], bl[2][4];
#pragma unroll
            for (int mi = 0; mi < 2; mi++) {
                int r = aRow + mi * 16;
                int c16 = kk * 2 + aHalf;
                uint32_t off = (uint32_t)(r * 128 + ((c16 ^ (r & 7)) * 16));
                LDSM_X4(ah[mi][0], ah[mi][1], ah[mi][2], ah[mi][3], base + off);
                LDSM_X4(al[mi][0], al[mi][1], al[mi][2], al[mi][3],
                        base + 16384u + off);
            }
#pragma unroll
            for (int np = 0; np < 2; np++) {
                int r = bRow + np * 16;
                int c16 = kk * 2 + bHalf;
                uint32_t off = (uint32_t)(r * 128 + ((c16 ^ (r & 7)) * 16));
                LDSM_X4(bh[np][0], bh[np][1], bh[np][2], bh[np][3],
                        base + 32768u + off);
                LDSM_X4(bl[np][0], bl[np][1], bl[np][2], bl[np][3],
                        base + 49152u + off);
            }
#pragma unroll
            for (int mi = 0; mi < 2; mi++)
#pragma unroll
                for (int ni = 0; ni < 4; ni++) {
                    const int np = ni >> 1, sub = (ni & 1) * 2;
                    mma16816(acc[mi][ni], ah[mi], bh[np][sub], bh[np][sub + 1]);
                    mma16816(acc[mi][ni], ah[mi], bl[np][sub], bl[np][sub + 1]);
                    mma16816(acc[mi][ni], al[mi], bh[np][sub], bh[np][sub + 1]);
                }
        }
        __syncthreads();
    }

    const int erow = rowBase + warpM * 32 + (lane >> 2);
    const int ecol0 = colBase + warpN * 32 + (lane & 3) * 2;
#pragma unroll
    for (int ni = 0; ni < 4; ni++) {
        const int col = ecol0 + ni * 8;
        const float sc = (col < qcols) ? QSCALE : 1.f;
        const float bx = bias[col], by = bias[col + 1];
#pragma unroll
        for (int mi = 0; mi < 2; mi++) {
            const int r0 = erow + mi * 16;
            float v0 = (acc[mi][ni][0] + bx) * sc;
            float v1 = (acc[mi][ni][1] + by) * sc;
            float v2 = (acc[mi][ni][2] + bx) * sc;
            float v3 = (acc[mi][ni][3] + by) * sc;
            if (Cf) {
                *(float2*)&Cf[(size_t)r0 * Ntot + col] = make_float2(v0, v1);
                *(float2*)&Cf[(size_t)(r0 + 8) * Ntot + col] = make_float2(v2, v3);
            } else {
                split2_store(v0, v1, Chi + (size_t)r0 * Ntot + col,
                             Clo + (size_t)r0 * Ntot + col);
                split2_store(v2, v3, Chi + (size_t)(r0 + 8) * Ntot + col,
                             Clo + (size_t)(r0 + 8) * Ntot + col);
            }
        }
    }
}

// ---------------------------------------------------------------------------
// Flash attention on mma.sync bf16 (hi/lo split, exp2-domain softmax).
// grid (S/128, B*H), 256 threads (8 warps x 16 q rows each).
// KV chunk = 64 rows, double buffered (round-4 proven shape).
// smem: Qhi 0, Qlo 16384; per buf (32768): KH 0, KL 8192, VH 16384, VL 24576.
// ---------------------------------------------------------------------------
#define FL_SMEM 98304
#define NCHUNK (S_LEN / 64)   // 32

__global__ __launch_bounds__(256, 1) void flash_mma_kernel(
    const __nv_bfloat16* __restrict__ qh, const __nv_bfloat16* __restrict__ ql,
    __nv_bfloat16* __restrict__ ohi, __nv_bfloat16* __restrict__ olo)
{
    extern __shared__ char sm_raw[];
    const uint32_t sb = smem_u32(sm_raw);
    const int tid = threadIdx.x;
    const int wid = tid >> 5;
    const int lane = tid & 31;
    const int q0 = blockIdx.x * 128;
    const int b = blockIdx.y >> 4;
    const int h = blockIdx.y & 15;
    const int qcol = h * HDIM;
    const int kcol = EMBED + h * HDIM;
    const int vcol = 2 * EMBED + h * HDIM;

    // ---- load Q tile (hi+lo): 2048 cp16 ----
#pragma unroll
    for (int i = 0; i < 8; i++) {
        int idx = tid + (i << 8);
        int mat = idx >> 10;            // 0: hi, 1: lo
        int r = (idx >> 3) & 127;
        int c16 = idx & 7;
        const __nv_bfloat16* sp = mat ? ql : qh;
        const void* src = sp + (size_t)((q0 + r) * 2 + b) * QKV_COLS + qcol + c16 * 8;
        uint32_t dst = sb + (uint32_t)(mat * 16384 + r * 128 +
                                       ((c16 ^ (r & 7)) * 16));
        cp16(dst, src);
    }
    CP_COMMIT();

    auto load_kv = [&](int j0, int buf) {
        const uint32_t base = sb + 32768u + (uint32_t)buf * 32768u;
#pragma unroll
        for (int i = 0; i < 8; i++) {
            int idx = tid + (i << 8);
            int mat = idx >> 9;         // 0:KH 1:KL 2:VH 3:VL
            int r = (idx >> 3) & 63;
            int c16 = idx & 7;
            const __nv_bfloat16* sp = (mat & 1) ? ql : qh;
            int colb = (mat >> 1) ? vcol : kcol;
            const void* src = sp + (size_t)((j0 + r) * 2 + b) * QKV_COLS + colb + c16 * 8;
            uint32_t dst = base + (uint32_t)(mat * 8192 + r * 128 +
                                             ((c16 ^ (r & 7)) * 16));
            cp16(dst, src);
        }
    };

    load_kv(0, 0);
    CP_COMMIT();
    CP_WAIT1();      // Q resident (chunk0 may still be in flight)
    __syncthreads();

    // ---- Q fragments into registers ----
    uint32_t aqh[4][4], aql[4][4];
    {
        int r = wid * 16 + (lane & 15);
#pragma unroll
        for (int kk = 0; kk < 4; kk++) {
            int c16 = kk * 2 + (lane >> 4);
            uint32_t off = (uint32_t)(r * 128 + ((c16 ^ (r & 7)) * 16));
            LDSM_X4(aqh[kk][0], aqh[kk][1], aqh[kk][2], aqh[kk][3], sb + off);
            LDSM_X4(aql[kk][0], aql[kk][1], aql[kk][2], aql[kk][3],
                    sb + 16384u + off);
        }
    }

    float O[8][4];
#pragma unroll
    for (int ni = 0; ni < 8; ni++)
#pragma unroll
        for (int j = 0; j < 4; j++) O[ni][j] = 0.f;
    float m0 = -1e30f, m1 = -1e30f, l0 = 0.f, l1 = 0.f;

    for (int s = 0; s < NCHUNK; s++) {
        if (s + 1 < NCHUNK) load_kv((s + 1) * 64, (s + 1) & 1);
        CP_COMMIT();
        CP_WAIT1();
        __syncthreads();

        const uint32_t kb = sb + 32768u + (uint32_t)(s & 1) * 32768u;

        // ---- QK^T ----
        float sc[8][4];
#pragma unroll
        for (int ni = 0; ni < 8; ni++)
#pragma unroll
            for (int j = 0; j < 4; j++) sc[ni][j] = 0.f;

#pragma unroll
        for (int kk = 0; kk < 4; kk++) {
            uint32_t kh[4][4], kl[4][4];
            int rb = ((lane >> 4) * 8) + (lane & 7);
            int c16 = kk * 2 + ((lane >> 3) & 1);
#pragma unroll
            for (int np = 0; np < 4; np++) {
                int r = rb + np * 16;
                uint32_t off = (uint32_t)(r * 128 + ((c16 ^ (r & 7)) * 16));
                LDSM_X4(kh[np][0], kh[np][1], kh[np][2], kh[np][3], kb + off);
                LDSM_X4(kl[np][0], kl[np][1], kl[np][2], kl[np][3],
                        kb + 8192u + off);
            }
#pragma unroll
            for (int ni = 0; ni < 8; ni++) {
                const int np = ni >> 1, sub = (ni & 1) * 2;
                mma16816(sc[ni], aqh[kk], kh[np][sub], kh[np][sub + 1]);
                mma16816(sc[ni], aqh[kk], kl[np][sub], kl[np][sub + 1]);
                mma16816(sc[ni], aql[kk], kh[np][sub], kh[np][sub + 1]);
            }
        }

        // ---- online softmax (exp2 domain; two row-halves per thread) ----
#pragma unroll
        for (int hh = 0; hh < 2; hh++) {
            const int j0 = hh * 2, j1 = hh * 2 + 1;
            float& m = hh ? m1 : m0;
            float& l = hh ? l1 : l0;
            float mx = -1e30f;
#pragma unroll
            for (int ni = 0; ni < 8; ni++)
                mx = fmaxf(mx, fmaxf(sc[ni][j0], sc[ni][j1]));
            mx = fmaxf(mx, __shfl_xor_sync(0xffffffffu, mx, 1));
            mx = fmaxf(mx, __shfl_xor_sync(0xffffffffu, mx, 2));
            float mn = fmaxf(m, mx);
            float alpha = fast_exp2(m - mn);
            m = mn;
            float sum = 0.f;
#pragma unroll
            for (int ni = 0; ni < 8; ni++) {
                sc[ni][j0] = fast_exp2(sc[ni][j0] - mn);
                sc[ni][j1] = fast_exp2(sc[ni][j1] - mn);
                sum += sc[ni][j0] + sc[ni][j1];
            }
            sum += __shfl_xor_sync(0xffffffffu, sum, 1);
            sum += __shfl_xor_sync(0xffffffffu, sum, 2);
            l = l * alpha + sum;
#pragma unroll
            for (int ni = 0; ni < 8; ni++) {
                O[ni][j0] *= alpha;
                O[ni][j1] *= alpha;
            }
        }

        // ---- P @ V ----
#pragma unroll
        for (int kk2 = 0; kk2 < 4; kk2++) {
            uint32_t ph[4], pl[4];
            pack_split(sc[2 * kk2][0],     sc[2 * kk2][1],     ph[0], pl[0]);
            pack_split(sc[2 * kk2][2],     sc[2 * kk2][3],     ph[1], pl[1]);
            pack_split(sc[2 * kk2 + 1][0], sc[2 * kk2 + 1][1], ph[2], pl[2]);
            pack_split(sc[2 * kk2 + 1][2], sc[2 * kk2 + 1][3], ph[3], pl[3]);

            uint32_t vh[4][4], vl[4][4];
            int g = lane >> 3;
            int row = kk2 * 16 + (g & 1) * 8 + (lane & 7);
#pragma unroll
            for (int g4 = 0; g4 < 4; g4++) {
                int c16 = g4 * 2 + (g >> 1);
                uint32_t off = (uint32_t)(row * 128 + ((c16 ^ (row & 7)) * 16));
                LDSM_X4_T(vh[g4][0], vh[g4][1], vh[g4][2], vh[g4][3],
                          kb + 16384u + off);
                LDSM_X4_T(vl[g4][0], vl[g4][1], vl[g4][2], vl[g4][3],
                          kb + 24576u + off);
            }
#pragma unroll
            for (int ni = 0; ni < 8; ni++) {
                const int g4 = ni >> 1, sub = (ni & 1) * 2;
                mma16816(O[ni], ph, vh[g4][sub], vh[g4][sub + 1]);
                mma16816(O[ni], ph, vl[g4][sub], vl[g4][sub + 1]);
                mma16816(O[ni], pl, vh[g4][sub], vh[g4][sub + 1]);
            }
        }
        __syncthreads();
    }

    // ---- epilogue: normalize, split hi/lo, store ----
    const float inv0 = 1.f / l0;
    const float inv1 = 1.f / l1;
    const int sA = q0 + wid * 16 + (lane >> 2);
    const size_t rowA = (size_t)(sA * 2 + b) * EMBED;
    const size_t rowB = (size_t)((sA + 8) * 2 + b) * EMBED;
    const int colb = h * HDIM + (lane & 3) * 2;
#pragma unroll
    for (int ni = 0; ni < 8; ni++) {
        const int col = colb + ni * 8;
        split2_store(O[ni][0] * inv0, O[ni][1] * inv0,
                     ohi + rowA + col, olo + rowA + col);
        split2_store(O[ni][2] * inv1, O[ni][3] * inv1,
                     ohi + rowB + col, olo + rowB + col);
    }
}

// ---------------------------------------------------------------------------
extern "C" void kernel_launch(void* const* d_in, const int* in_sizes, int n_in,
                              void* d_out, int out_size)
{
    (void)in_sizes; (void)n_in; (void)out_size;
    const float* x    = (const float*)d_in[0];
    const float* Win  = (const float*)d_in[1];
    const float* bin  = (const float*)d_in[2];
    const float* Wout = (const float*)d_in[3];
    const float* bout = (const float*)d_in[4];
    float* out = (float*)d_out;

    __nv_bfloat16 *xhi, *xlo, *w1hi, *w1lo, *w2hi, *w2lo;
    __nv_bfloat16 *qkvhi, *qkvlo, *ahi, *alo;
    cudaGetSymbolAddress((void**)&xhi, g_xhi);
    cudaGetSymbolAddress((void**)&xlo, g_xlo);
    cudaGetSymbolAddress((void**)&w1hi, g_w1hi);
    cudaGetSymbolAddress((void**)&w1lo, g_w1lo);
    cudaGetSymbolAddress((void**)&w2hi, g_w2hi);
    cudaGetSymbolAddress((void**)&w2lo, g_w2lo);
    cudaGetSymbolAddress((void**)&qkvhi, g_qkvhi);
    cudaGetSymbolAddress((void**)&qkvlo, g_qkvlo);
    cudaGetSymbolAddress((void**)&ahi, g_ahi);
    cudaGetSymbolAddress((void**)&alo, g_alo);

    cudaFuncSetAttribute(gemm_mma_kernel,
                         cudaFuncAttributeMaxDynamicSharedMemorySize, GEMM_SMEM);
    cudaFuncSetAttribute(flash_mma_kernel,
                         cudaFuncAttributeMaxDynamicSharedMemorySize, FL_SMEM);

    // 0) fp32 -> bf16 hi/lo splits for inputs
    split_bf16_kernel<<<(M_ROWS * EMBED) / 1024, 256>>>(
        (const float4*)x, (ushort4*)xhi, (ushort4*)xlo);
    split_bf16_kernel<<<(QKV_COLS * EMBED) / 1024, 256>>>(
        (const float4*)Win, (ushort4*)w1hi, (ushort4*)w1lo);
    split_bf16_kernel<<<(EMBED * EMBED) / 1024, 256>>>(
        (const float4*)Wout, (ushort4*)w2hi, (ushort4*)w2lo);

    // 1) QKV projection -> bf16 hi/lo qkv (Q pre-scaled by 0.125*log2e)
    gemm_mma_kernel<<<dim3(QKV_COLS / 128, M_ROWS / 128), 512, GEMM_SMEM>>>(
        xhi, xlo, w1hi, w1lo, bin, nullptr, qkvhi, qkvlo, QKV_COLS, EMBED);

    // 2) Flash attention on tensor cores -> bf16 hi/lo attn
    flash_mma_kernel<<<dim3(S_LEN / 128, BATCH * HEADS), 256, FL_SMEM>>>(
        qkvhi, qkvlo, ahi, alo);

    // 3) Output projection -> fp32 out
    gemm_mma_kernel<<<dim3(EMBED / 128, M_ROWS / 128), 512, GEMM_SMEM>>>(
        ahi, alo, w2hi, w2lo, bout, out, nullptr, nullptr, EMBED, 0);
}

// round 7
// speedup vs baseline: 1.4688x; 1.0316x over previous
#include <cuda_runtime.h>
#include <cuda_bf16.h>
#include <cstdint>

// Problem constants
#define S_LEN 2048
#define BATCH 2
#define EMBED 1024
#define HEADS 16
#define HDIM  64
#define M_ROWS (S_LEN * BATCH)        // 4096
#define QKV_COLS (3 * EMBED)          // 3072

// Q scale folded with log2(e) so softmax can use exp2 directly
#define QSCALE 0.18033688011112042f   // 0.125 * log2(e)

// ---------------------------------------------------------------------------
// Scratch (device globals; no allocation in kernel_launch)
// ---------------------------------------------------------------------------
__device__ __align__(16) __nv_bfloat16 g_xhi[(size_t)M_ROWS * EMBED];
__device__ __align__(16) __nv_bfloat16 g_xlo[(size_t)M_ROWS * EMBED];
__device__ __align__(16) __nv_bfloat16 g_w1hi[(size_t)QKV_COLS * EMBED];
__device__ __align__(16) __nv_bfloat16 g_w1lo[(size_t)QKV_COLS * EMBED];
__device__ __align__(16) __nv_bfloat16 g_w2hi[(size_t)EMBED * EMBED];
__device__ __align__(16) __nv_bfloat16 g_w2lo[(size_t)EMBED * EMBED];
__device__ __align__(16) __nv_bfloat16 g_qkvhi[(size_t)M_ROWS * QKV_COLS];
__device__ __align__(16) __nv_bfloat16 g_qkvlo[(size_t)M_ROWS * QKV_COLS];
__device__ __align__(16) __nv_bfloat16 g_ahi[(size_t)M_ROWS * EMBED];
__device__ __align__(16) __nv_bfloat16 g_alo[(size_t)M_ROWS * EMBED];

// ---------------------------------------------------------------------------
// PTX helpers (baseline compute_103-safe: mma.sync + ldmatrix + cp.async)
// ---------------------------------------------------------------------------
__device__ __forceinline__ uint32_t smem_u32(const void* p) {
    uint32_t addr;
    asm("{ .reg .u64 t; cvta.to.shared.u64 t, %1; cvt.u32.u64 %0, t; }"
        : "=r"(addr) : "l"(p));
    return addr;
}

__device__ __forceinline__ void cp16(uint32_t dst, const void* src) {
    asm volatile("cp.async.cg.shared.global [%0], [%1], 16;" :: "r"(dst), "l"(src));
}
#define CP_COMMIT() asm volatile("cp.async.commit_group;" ::: "memory")
#define CP_WAIT1()  asm volatile("cp.async.wait_group 1;" ::: "memory")
#define CP_WAIT2()  asm volatile("cp.async.wait_group 2;" ::: "memory")

#define LDSM_X4(r0, r1, r2, r3, addr) \
    asm volatile("ldmatrix.sync.aligned.m8n8.x4.shared.b16 {%0,%1,%2,%3}, [%4];" \
        : "=r"(r0), "=r"(r1), "=r"(r2), "=r"(r3) : "r"(addr))

#define LDSM_X4_T(r0, r1, r2, r3, addr) \
    asm volatile("ldmatrix.sync.aligned.m8n8.x4.trans.shared.b16 {%0,%1,%2,%3}, [%4];" \
        : "=r"(r0), "=r"(r1), "=r"(r2), "=r"(r3) : "r"(addr))

__device__ __forceinline__ void mma16816(float* c, const uint32_t* a,
                                         const uint32_t b0, const uint32_t b1) {
    asm volatile(
        "mma.sync.aligned.m16n8k16.row.col.f32.bf16.bf16.f32 "
        "{%0,%1,%2,%3}, {%4,%5,%6,%7}, {%8,%9}, {%0,%1,%2,%3};"
        : "+f"(c[0]), "+f"(c[1]), "+f"(c[2]), "+f"(c[3])
        : "r"(a[0]), "r"(a[1]), "r"(a[2]), "r"(a[3]), "r"(b0), "r"(b1));
}

__device__ __forceinline__ float fast_exp2(float x) {
    float y;
    asm("ex2.approx.f32 %0, %1;" : "=f"(y) : "f"(x));
    return y;
}

__device__ __forceinline__ void pack_split(float f0, float f1,
                                           uint32_t& hi, uint32_t& lo) {
    __nv_bfloat162 h = __floats2bfloat162_rn(f0, f1);
    float2 hf = __bfloat1622float2(h);
    __nv_bfloat162 l = __floats2bfloat162_rn(f0 - hf.x, f1 - hf.y);
    hi = *reinterpret_cast<uint32_t*>(&h);
    lo = *reinterpret_cast<uint32_t*>(&l);
}

__device__ __forceinline__ void split2_store(float v0, float v1,
                                             __nv_bfloat16* hip,
                                             __nv_bfloat16* lop) {
    __nv_bfloat162 h = __floats2bfloat162_rn(v0, v1);
    float2 hf = __bfloat1622float2(h);
    __nv_bfloat162 l = __floats2bfloat162_rn(v0 - hf.x, v1 - hf.y);
    *reinterpret_cast<__nv_bfloat162*>(hip) = h;
    *reinterpret_cast<__nv_bfloat162*>(lop) = l;
}

// ---------------------------------------------------------------------------
// fp32 -> bf16 hi/lo split (vectorized by 4)
// ---------------------------------------------------------------------------
__global__ __launch_bounds__(256) void split_bf16_kernel(
    const float4* __restrict__ in, ushort4* __restrict__ hi,
    ushort4* __restrict__ lo)
{
    int i = blockIdx.x * blockDim.x + threadIdx.x;
    float4 v = in[i];
    __nv_bfloat16 h0 = __float2bfloat16(v.x);
    __nv_bfloat16 h1 = __float2bfloat16(v.y);
    __nv_bfloat16 h2 = __float2bfloat16(v.z);
    __nv_bfloat16 h3 = __float2bfloat16(v.w);
    __nv_bfloat16 l0 = __float2bfloat16(v.x - __bfloat162float(h0));
    __nv_bfloat16 l1 = __float2bfloat16(v.y - __bfloat162float(h1));
    __nv_bfloat16 l2 = __float2bfloat16(v.z - __bfloat162float(h2));
    __nv_bfloat16 l3 = __float2bfloat16(v.w - __bfloat162float(h3));
    hi[i] = make_ushort4(__bfloat16_as_ushort(h0), __bfloat16_as_ushort(h1),
                         __bfloat16_as_ushort(h2), __bfloat16_as_ushort(h3));
    lo[i] = make_ushort4(__bfloat16_as_ushort(l0), __bfloat16_as_ushort(l1),
                         __bfloat16_as_ushort(l2), __bfloat16_as_ushort(l3));
}

// ---------------------------------------------------------------------------
// mma.sync GEMM:  C = Ahi*Whi^T + Ahi*Wlo^T + Alo*Whi^T + bias
// CTA tile 128x128, 16 warps (4 M x 4 N), warp tile 32x32, 512 threads.
// K staged 64 elems; 3-buffer cp.async ring, ONE barrier per stage.
// grid = (Ntot/128, M/128).  Columns < qcols scaled by QSCALE.
// ---------------------------------------------------------------------------
#define GK 1024
#define KSTEP 64
#define NSTAGE (GK / KSTEP)          // 16
#define STAGE_BYTES 65536            // 4 mats x 128 rows x 128B
#define GEMM_SMEM (3 * STAGE_BYTES)  // 196608

__global__ __launch_bounds__(512, 1) void gemm_mma_kernel(
    const __nv_bfloat16* __restrict__ Ahi, const __nv_bfloat16* __restrict__ Alo,
    const __nv_bfloat16* __restrict__ Whi, const __nv_bfloat16* __restrict__ Wlo,
    const float* __restrict__ bias, float* __restrict__ Cf,
    __nv_bfloat16* __restrict__ Chi, __nv_bfloat16* __restrict__ Clo,
    int Ntot, int qcols)
{
    extern __shared__ char sm_raw[];
    const uint32_t smem_base = smem_u32(sm_raw);
    const int tid = threadIdx.x;
    const int wid = tid >> 5;
    const int lane = tid & 31;
    const int warpM = wid & 3;          // 4 warps over M
    const int warpN = wid >> 2;         // 4 warps over N
    const int rowBase = blockIdx.y * 128;
    const int colBase = blockIdx.x * 128;

    // stage layout: Ahi 0, Alo 16384, Whi 32768, Wlo 49152
    auto load_stage = [&](int s, int buf) {
        const int k0 = s * KSTEP;
        const uint32_t base = smem_base + (uint32_t)buf * STAGE_BYTES;
#pragma unroll
        for (int i = 0; i < 8; i++) {
            int idx = tid + (i << 9);          // 0..4095
            int mat = idx >> 10;               // 0:Ahi 1:Alo 2:Whi 3:Wlo
            int r   = (idx >> 3) & 127;
            int c16 = idx & 7;
            const __nv_bfloat16* srcb =
                (mat == 0) ? Ahi : (mat == 1) ? Alo : (mat == 2) ? Whi : Wlo;
            int rowg = ((mat < 2) ? rowBase : colBase) + r;
            const void* src = srcb + (size_t)rowg * GK + k0 + c16 * 8;
            uint32_t dst = base + (uint32_t)(mat * 16384 + r * 128 +
                                             ((c16 ^ (r & 7)) * 16));
            cp16(dst, src);
        }
    };

    float acc[2][4][4];
#pragma unroll
    for (int mi = 0; mi < 2; mi++)
#pragma unroll
        for (int ni = 0; ni < 4; ni++)
#pragma unroll
            for (int j = 0; j < 4; j++) acc[mi][ni][j] = 0.f;

    const int aRow = warpM * 32 + (lane & 15);
    const int aHalf = lane >> 4;
    const int bRow = warpN * 32 + ((lane >> 4) * 8) + (lane & 7);
    const int bHalf = (lane >> 3) & 1;

    // prologue: 2 stages in flight
    load_stage(0, 0); CP_COMMIT();
    load_stage(1, 1); CP_COMMIT();

    int buf = 0;
    for (int s = 0; s < NSTAGE; s++) {
        CP_WAIT1();          // stage s resident (s+1 may be in flight)
        __syncthreads();     // also: everyone done reading ring slot (s-1)%3
        if (s + 2 < NSTAGE) {
            int nbuf = buf + 2; if (nbuf >= 3) nbuf -= 3;
            load_stage(s + 2, nbuf);
            CP_COMMIT();
        }

        const uint32_t base = smem_base + (uint32_t)buf * STAGE_BYTES;
#pragma unroll
        for (int kk = 0; kk < 4; kk++) {
            uint32_t ah[2][4], al[2][4], bh[2][4], bl[2][4];
#pragma unroll
            for (int mi = 0; mi < 2; mi++) {
                int r = aRow + mi * 16;
                int c16 = kk * 2 + aHalf;
                uint32_t off = (uint32_t)(r * 128 + ((c16 ^ (r & 7)) * 16));
                LDSM_X4(ah[mi][0], ah[mi][1], ah[mi][2], ah[mi][3], base + off);
                LDSM_X4(al[mi][0], al[mi][1], al[mi][2], al[mi][3],
                        base + 16384u + off);
            }
#pragma unroll
            for (int np = 0; np < 2; np++) {
                int r = bRow + np * 16;
                int c16 = kk * 2 + bHalf;
                uint32_t off = (uint32_t)(r * 128 + ((c16 ^ (r & 7)) * 16));
                LDSM_X4(bh[np][0], bh[np][1], bh[np][2], bh[np][3],
                        base + 32768u + off);
                LDSM_X4(bl[np][0], bl[np][1], bl[np][2], bl[np][3],
                        base + 49152u + off);
            }
#pragma unroll
            for (int mi = 0; mi < 2; mi++)
#pragma unroll
                for (int ni = 0; ni < 4; ni++) {
                    const int np = ni >> 1, sub = (ni & 1) * 2;
                    mma16816(acc[mi][ni], ah[mi], bh[np][sub], bh[np][sub + 1]);
                    mma16816(acc[mi][ni], ah[mi], bl[np][sub], bl[np][sub + 1]);
                    mma16816(acc[mi][ni], al[mi], bh[np][sub], bh[np][sub + 1]);
                }
        }
        if (++buf >= 3) buf = 0;
    }

    const int erow = rowBase + warpM * 32 + (lane >> 2);
    const int ecol0 = colBase + warpN * 32 + (lane & 3) * 2;
#pragma unroll
    for (int ni = 0; ni < 4; ni++) {
        const int col = ecol0 + ni * 8;
        const float sc = (col < qcols) ? QSCALE : 1.f;
        const float bx = bias[col], by = bias[col + 1];
#pragma unroll
        for (int mi = 0; mi < 2; mi++) {
            const int r0 = erow + mi * 16;
            float v0 = (acc[mi][ni][0] + bx) * sc;
            float v1 = (acc[mi][ni][1] + by) * sc;
            float v2 = (acc[mi][ni][2] + bx) * sc;
            float v3 = (acc[mi][ni][3] + by) * sc;
            if (Cf) {
                *(float2*)&Cf[(size_t)r0 * Ntot + col] = make_float2(v0, v1);
                *(float2*)&Cf[(size_t)(r0 + 8) * Ntot + col] = make_float2(v2, v3);
            } else {
                split2_store(v0, v1, Chi + (size_t)r0 * Ntot + col,
                             Clo + (size_t)r0 * Ntot + col);
                split2_store(v2, v3, Chi + (size_t)(r0 + 8) * Ntot + col,
                             Clo + (size_t)(r0 + 8) * Ntot + col);
            }
        }
    }
}

// ---------------------------------------------------------------------------
// Flash attention on mma.sync bf16 (hi/lo split, exp2-domain softmax).
// grid (S/128, B*H), 256 threads (8 warps x 16 q rows each).
// KV chunk = 64 rows; 3-buffer cp.async ring, ONE barrier per chunk.
// smem: Qhi 0, Qlo 16384; ring at 32768, 3 x 32768.
// ---------------------------------------------------------------------------
#define FL_SMEM 131072
#define NCHUNK (S_LEN / 64)   // 32

__global__ __launch_bounds__(256, 1) void flash_mma_kernel(
    const __nv_bfloat16* __restrict__ qh, const __nv_bfloat16* __restrict__ ql,
    __nv_bfloat16* __restrict__ ohi, __nv_bfloat16* __restrict__ olo)
{
    extern __shared__ char sm_raw[];
    const uint32_t sb = smem_u32(sm_raw);
    const int tid = threadIdx.x;
    const int wid = tid >> 5;
    const int lane = tid & 31;
    const int q0 = blockIdx.x * 128;
    const int b = blockIdx.y >> 4;
    const int h = blockIdx.y & 15;
    const int qcol = h * HDIM;
    const int kcol = EMBED + h * HDIM;
    const int vcol = 2 * EMBED + h * HDIM;

    // ---- load Q tile (hi+lo): 2048 cp16 (group 0) ----
#pragma unroll
    for (int i = 0; i < 8; i++) {
        int idx = tid + (i << 8);
        int mat = idx >> 10;            // 0: hi, 1: lo
        int r = (idx >> 3) & 127;
        int c16 = idx & 7;
        const __nv_bfloat16* sp = mat ? ql : qh;
        const void* src = sp + (size_t)((q0 + r) * 2 + b) * QKV_COLS + qcol + c16 * 8;
        uint32_t dst = sb + (uint32_t)(mat * 16384 + r * 128 +
                                       ((c16 ^ (r & 7)) * 16));
        cp16(dst, src);
    }
    CP_COMMIT();

    auto load_kv = [&](int j0, int buf) {
        const uint32_t base = sb + 32768u + (uint32_t)buf * 32768u;
#pragma unroll
        for (int i = 0; i < 8; i++) {
            int idx = tid + (i << 8);
            int mat = idx >> 9;         // 0:KH 1:KL 2:VH 3:VL
            int r = (idx >> 3) & 63;
            int c16 = idx & 7;
            const __nv_bfloat16* sp = (mat & 1) ? ql : qh;
            int colb = (mat >> 1) ? vcol : kcol;
            const void* src = sp + (size_t)((j0 + r) * 2 + b) * QKV_COLS + colb + c16 * 8;
            uint32_t dst = base + (uint32_t)(mat * 8192 + r * 128 +
                                             ((c16 ^ (r & 7)) * 16));
            cp16(dst, src);
        }
    };

    // prologue: kv chunks 0 and 1 in flight
    load_kv(0, 0);  CP_COMMIT();
    load_kv(64, 1); CP_COMMIT();

    CP_WAIT2();      // Q resident (kv0/kv1 may be in flight)
    __syncthreads();

    // ---- Q fragments into registers ----
    uint32_t aqh[4][4], aql[4][4];
    {
        int r = wid * 16 + (lane & 15);
#pragma unroll
        for (int kk = 0; kk < 4; kk++) {
            int c16 = kk * 2 + (lane >> 4);
            uint32_t off = (uint32_t)(r * 128 + ((c16 ^ (r & 7)) * 16));
            LDSM_X4(aqh[kk][0], aqh[kk][1], aqh[kk][2], aqh[kk][3], sb + off);
            LDSM_X4(aql[kk][0], aql[kk][1], aql[kk][2], aql[kk][3],
                    sb + 16384u + off);
        }
    }

    float O[8][4];
#pragma unroll
    for (int ni = 0; ni < 8; ni++)
#pragma unroll
        for (int j = 0; j < 4; j++) O[ni][j] = 0.f;
    float m0 = -1e30f, m1 = -1e30f, l0 = 0.f, l1 = 0.f;

    int buf = 0;
    for (int s = 0; s < NCHUNK; s++) {
        CP_WAIT1();          // chunk s resident
        __syncthreads();     // ring slot (s-1)%3 fully consumed by all warps
        if (s + 2 < NCHUNK) {
            int nbuf = buf + 2; if (nbuf >= 3) nbuf -= 3;
            load_kv((s + 2) * 64, nbuf);
            CP_COMMIT();
        }

        const uint32_t kb = sb + 32768u + (uint32_t)buf * 32768u;

        // ---- QK^T ----
        float sc[8][4];
#pragma unroll
        for (int ni = 0; ni < 8; ni++)
#pragma unroll
            for (int j = 0; j < 4; j++) sc[ni][j] = 0.f;

#pragma unroll
        for (int kk = 0; kk < 4; kk++) {
            uint32_t kh[4][4], kl[4][4];
            int rb = ((lane >> 4) * 8) + (lane & 7);
            int c16 = kk * 2 + ((lane >> 3) & 1);
#pragma unroll
            for (int np = 0; np < 4; np++) {
                int r = rb + np * 16;
                uint32_t off = (uint32_t)(r * 128 + ((c16 ^ (r & 7)) * 16));
                LDSM_X4(kh[np][0], kh[np][1], kh[np][2], kh[np][3], kb + off);
                LDSM_X4(kl[np][0], kl[np][1], kl[np][2], kl[np][3],
                        kb + 8192u + off);
            }
#pragma unroll
            for (int ni = 0; ni < 8; ni++) {
                const int np = ni >> 1, sub = (ni & 1) * 2;
                mma16816(sc[ni], aqh[kk], kh[np][sub], kh[np][sub + 1]);
                mma16816(sc[ni], aqh[kk], kl[np][sub], kl[np][sub + 1]);
                mma16816(sc[ni], aql[kk], kh[np][sub], kh[np][sub + 1]);
            }
        }

        // ---- online softmax (exp2 domain; two row-halves per thread) ----
#pragma unroll
        for (int hh = 0; hh < 2; hh++) {
            const int j0 = hh * 2, j1 = hh * 2 + 1;
            float& m = hh ? m1 : m0;
            float& l = hh ? l1 : l0;
            float mx = -1e30f;
#pragma unroll
            for (int ni = 0; ni < 8; ni++)
                mx = fmaxf(mx, fmaxf(sc[ni][j0], sc[ni][j1]));
            mx = fmaxf(mx, __shfl_xor_sync(0xffffffffu, mx, 1));
            mx = fmaxf(mx, __shfl_xor_sync(0xffffffffu, mx, 2));
            float mn = fmaxf(m, mx);
            float alpha = fast_exp2(m - mn);
            m = mn;
            float sum = 0.f;
#pragma unroll
            for (int ni = 0; ni < 8; ni++) {
                sc[ni][j0] = fast_exp2(sc[ni][j0] - mn);
                sc[ni][j1] = fast_exp2(sc[ni][j1] - mn);
                sum += sc[ni][j0] + sc[ni][j1];
            }
            sum += __shfl_xor_sync(0xffffffffu, sum, 1);
            sum += __shfl_xor_sync(0xffffffffu, sum, 2);
            l = l * alpha + sum;
#pragma unroll
            for (int ni = 0; ni < 8; ni++) {
                O[ni][j0] *= alpha;
                O[ni][j1] *= alpha;
            }
        }

        // ---- P @ V ----
#pragma unroll
        for (int kk2 = 0; kk2 < 4; kk2++) {
            uint32_t ph[4], pl[4];
            pack_split(sc[2 * kk2][0],     sc[2 * kk2][1],     ph[0], pl[0]);
            pack_split(sc[2 * kk2][2],     sc[2 * kk2][3],     ph[1], pl[1]);
            pack_split(sc[2 * kk2 + 1][0], sc[2 * kk2 + 1][1], ph[2], pl[2]);
            pack_split(sc[2 * kk2 + 1][2], sc[2 * kk2 + 1][3], ph[3], pl[3]);

            uint32_t vh[4][4], vl[4][4];
            int g = lane >> 3;
            int row = kk2 * 16 + (g & 1) * 8 + (lane & 7);
#pragma unroll
            for (int g4 = 0; g4 < 4; g4++) {
                int c16 = g4 * 2 + (g >> 1);
                uint32_t off = (uint32_t)(row * 128 + ((c16 ^ (row & 7)) * 16));
                LDSM_X4_T(vh[g4][0], vh[g4][1], vh[g4][2], vh[g4][3],
                          kb + 16384u + off);
                LDSM_X4_T(vl[g4][0], vl[g4][1], vl[g4][2], vl[g4][3],
                          kb + 24576u + off);
            }
#pragma unroll
            for (int ni = 0; ni < 8; ni++) {
                const int g4 = ni >> 1, sub = (ni & 1) * 2;
                mma16816(O[ni], ph, vh[g4][sub], vh[g4][sub + 1]);
                mma16816(O[ni], ph, vl[g4][sub], vl[g4][sub + 1]);
                mma16816(O[ni], pl, vh[g4][sub], vh[g4][sub + 1]);
            }
        }
        if (++buf >= 3) buf = 0;
    }

    // ---- epilogue: normalize, split hi/lo, store ----
    const float inv0 = 1.f / l0;
    const float inv1 = 1.f / l1;
    const int sA = q0 + wid * 16 + (lane >> 2);
    const size_t rowA = (size_t)(sA * 2 + b) * EMBED;
    const size_t rowB = (size_t)((sA + 8) * 2 + b) * EMBED;
    const int colb = h * HDIM + (lane & 3) * 2;
#pragma unroll
    for (int ni = 0; ni < 8; ni++) {
        const int col = colb + ni * 8;
        split2_store(O[ni][0] * inv0, O[ni][1] * inv0,
                     ohi + rowA + col, olo + rowA + col);
        split2_store(O[ni][2] * inv1, O[ni][3] * inv1,
                     ohi + rowB + col, olo + rowB + col);
    }
}

// ---------------------------------------------------------------------------
extern "C" void kernel_launch(void* const* d_in, const int* in_sizes, int n_in,
                              void* d_out, int out_size)
{
    (void)in_sizes; (void)n_in; (void)out_size;
    const float* x    = (const float*)d_in[0];
    const float* Win  = (const float*)d_in[1];
    const float* bin  = (const float*)d_in[2];
    const float* Wout = (const float*)d_in[3];
    const float* bout = (const float*)d_in[4];
    float* out = (float*)d_out;

    __nv_bfloat16 *xhi, *xlo, *w1hi, *w1lo, *w2hi, *w2lo;
    __nv_bfloat16 *qkvhi, *qkvlo, *ahi, *alo;
    cudaGetSymbolAddress((void**)&xhi, g_xhi);
    cudaGetSymbolAddress((void**)&xlo, g_xlo);
    cudaGetSymbolAddress((void**)&w1hi, g_w1hi);
    cudaGetSymbolAddress((void**)&w1lo, g_w1lo);
    cudaGetSymbolAddress((void**)&w2hi, g_w2hi);
    cudaGetSymbolAddress((void**)&w2lo, g_w2lo);
    cudaGetSymbolAddress((void**)&qkvhi, g_qkvhi);
    cudaGetSymbolAddress((void**)&qkvlo, g_qkvlo);
    cudaGetSymbolAddress((void**)&ahi, g_ahi);
    cudaGetSymbolAddress((void**)&alo, g_alo);

    cudaFuncSetAttribute(gemm_mma_kernel,
                         cudaFuncAttributeMaxDynamicSharedMemorySize, GEMM_SMEM);
    cudaFuncSetAttribute(flash_mma_kernel,
                         cudaFuncAttributeMaxDynamicSharedMemorySize, FL_SMEM);

    // 0) fp32 -> bf16 hi/lo splits for inputs
    split_bf16_kernel<<<(M_ROWS * EMBED) / 1024, 256>>>(
        (const float4*)x, (ushort4*)xhi, (ushort4*)xlo);
    split_bf16_kernel<<<(QKV_COLS * EMBED) / 1024, 256>>>(
        (const float4*)Win, (ushort4*)w1hi, (ushort4*)w1lo);
    split_bf16_kernel<<<(EMBED * EMBED) / 1024, 256>>>(
        (const float4*)Wout, (ushort4*)w2hi, (ushort4*)w2lo);

    // 1) QKV projection -> bf16 hi/lo qkv (Q pre-scaled by 0.125*log2e)
    gemm_mma_kernel<<<dim3(QKV_COLS / 128, M_ROWS / 128), 512, GEMM_SMEM>>>(
        xhi, xlo, w1hi, w1lo, bin, nullptr, qkvhi, qkvlo, QKV_COLS, EMBED);

    // 2) Flash attention on tensor cores -> bf16 hi/lo attn
    flash_mma_kernel<<<dim3(S_LEN / 128, BATCH * HEADS), 256, FL_SMEM>>>(
        qkvhi, qkvlo, ahi, alo);

    // 3) Output projection -> fp32 out
    gemm_mma_kernel<<<dim3(EMBED / 128, M_ROWS / 128), 512, GEMM_SMEM>>>(
        ahi, alo, w2hi, w2lo, bout, out, nullptr, nullptr, EMBED, 0);
}

// round 8
// speedup vs baseline: 3.3825x; 2.3028x over previous
#include <cuda_runtime.h>
#include <cuda_fp16.h>
#include <cstdint>

// Problem constants
#define S_LEN 2048
#define BATCH 2
#define EMBED 1024
#define HEADS 16
#define HDIM  64
#define M_ROWS (S_LEN * BATCH)        // 4096
#define QKV_COLS (3 * EMBED)          // 3072

// Q scale folded with log2(e) so softmax can use exp2 directly
#define QSCALE 0.18033688011112042f   // 0.125 * log2(e)

// ---------------------------------------------------------------------------
// Scratch (device globals; no allocation in kernel_launch)
// ---------------------------------------------------------------------------
__device__ __align__(16) __half g_xh[(size_t)M_ROWS * EMBED];
__device__ __align__(16) __half g_w1h[(size_t)QKV_COLS * EMBED];
__device__ __align__(16) __half g_w2h[(size_t)EMBED * EMBED];
__device__ __align__(16) __half g_qkvh[(size_t)M_ROWS * QKV_COLS];
__device__ __align__(16) __half g_ah[(size_t)M_ROWS * EMBED];

// ---------------------------------------------------------------------------
// PTX helpers (baseline compute_103-safe: mma.sync + ldmatrix + cp.async)
// ---------------------------------------------------------------------------
__device__ __forceinline__ uint32_t smem_u32(const void* p) {
    uint32_t addr;
    asm("{ .reg .u64 t; cvta.to.shared.u64 t, %1; cvt.u32.u64 %0, t; }"
        : "=r"(addr) : "l"(p));
    return addr;
}

__device__ __forceinline__ void cp16(uint32_t dst, const void* src) {
    asm volatile("cp.async.cg.shared.global [%0], [%1], 16;" :: "r"(dst), "l"(src));
}
#define CP_COMMIT() asm volatile("cp.async.commit_group;" ::: "memory")
#define CP_WAIT1()  asm volatile("cp.async.wait_group 1;" ::: "memory")
#define CP_WAIT2()  asm volatile("cp.async.wait_group 2;" ::: "memory")

#define LDSM_X4(r0, r1, r2, r3, addr) \
    asm volatile("ldmatrix.sync.aligned.m8n8.x4.shared.b16 {%0,%1,%2,%3}, [%4];" \
        : "=r"(r0), "=r"(r1), "=r"(r2), "=r"(r3) : "r"(addr))

#define LDSM_X4_T(r0, r1, r2, r3, addr) \
    asm volatile("ldmatrix.sync.aligned.m8n8.x4.trans.shared.b16 {%0,%1,%2,%3}, [%4];" \
        : "=r"(r0), "=r"(r1), "=r"(r2), "=r"(r3) : "r"(addr))

__device__ __forceinline__ void mma16816(float* c, const uint32_t* a,
                                         const uint32_t b0, const uint32_t b1) {
    asm volatile(
        "mma.sync.aligned.m16n8k16.row.col.f32.f16.f16.f32 "
        "{%0,%1,%2,%3}, {%4,%5,%6,%7}, {%8,%9}, {%0,%1,%2,%3};"
        : "+f"(c[0]), "+f"(c[1]), "+f"(c[2]), "+f"(c[3])
        : "r"(a[0]), "r"(a[1]), "r"(a[2]), "r"(a[3]), "r"(b0), "r"(b1));
}

__device__ __forceinline__ float fast_exp2(float x) {
    float y;
    asm("ex2.approx.f32 %0, %1;" : "=f"(y) : "f"(x));
    return y;
}

__device__ __forceinline__ uint32_t pack_f16(float f0, float f1) {
    __half2 h = __floats2half2_rn(f0, f1);
    return *reinterpret_cast<uint32_t*>(&h);
}

// ---------------------------------------------------------------------------
// fp32 -> fp16 convert (vectorized by 4)
// ---------------------------------------------------------------------------
__global__ __launch_bounds__(256) void cvt_f16_kernel(
    const float4* __restrict__ in, uint2* __restrict__ out)
{
    int i = blockIdx.x * blockDim.x + threadIdx.x;
    float4 v = in[i];
    uint2 r;
    r.x = pack_f16(v.x, v.y);
    r.y = pack_f16(v.z, v.w);
    out[i] = r;
}

// ---------------------------------------------------------------------------
// mma.sync fp16 GEMM:  C[M,Ntot] = A[M,1024] * W[Ntot,1024]^T + bias
// CTA tile 128x256, 16 warps (4 M x 4 N), warp tile 32x64, 512 threads.
// K staged 64 elems; 3-buffer cp.async ring, ONE barrier per stage.
// grid = (Ntot/256, M/128).  Columns < qcols scaled by QSCALE.
// Output: Cf (fp32) or Ch (fp16).
// ---------------------------------------------------------------------------
#define GK 1024
#define KSTEP 64
#define NSTAGE (GK / KSTEP)          // 16
#define STAGE_BYTES 49152            // A 16KB + W 32KB
#define GEMM_SMEM (3 * STAGE_BYTES)  // 147456

__global__ __launch_bounds__(512, 1) void gemm_mma_kernel(
    const __half* __restrict__ A, const __half* __restrict__ W,
    const float* __restrict__ bias, float* __restrict__ Cf,
    __half* __restrict__ Ch, int Ntot, int qcols)
{
    extern __shared__ char sm_raw[];
    const uint32_t smem_base = smem_u32(sm_raw);
    const int tid = threadIdx.x;
    const int wid = tid >> 5;
    const int lane = tid & 31;
    const int warpM = wid & 3;          // 4 warps over M (32 rows each)
    const int warpN = wid >> 2;         // 4 warps over N (64 cols each)
    const int rowBase = blockIdx.y * 128;
    const int colBase = blockIdx.x * 256;

    // stage layout: A 0 (16KB), W 16384 (32KB)
    auto load_stage = [&](int s, int buf) {
        const int k0 = s * KSTEP;
        const uint32_t base = smem_base + (uint32_t)buf * STAGE_BYTES;
#pragma unroll
        for (int i = 0; i < 6; i++) {
            int idx = tid + (i << 9);          // 0..3071
            if (idx < 1024) {
                int r = idx >> 3, c16 = idx & 7;
                const void* src = A + (size_t)(rowBase + r) * GK + k0 + c16 * 8;
                cp16(base + (uint32_t)(r * 128 + ((c16 ^ (r & 7)) * 16)), src);
            } else {
                int idx2 = idx - 1024;         // 0..2047
                int r = idx2 >> 3, c16 = idx2 & 7;
                const void* src = W + (size_t)(colBase + r) * GK + k0 + c16 * 8;
                cp16(base + 16384u + (uint32_t)(r * 128 + ((c16 ^ (r & 7)) * 16)),
                     src);
            }
        }
    };

    float acc[2][8][4];
#pragma unroll
    for (int mi = 0; mi < 2; mi++)
#pragma unroll
        for (int ni = 0; ni < 8; ni++)
#pragma unroll
            for (int j = 0; j < 4; j++) acc[mi][ni][j] = 0.f;

    const int aRow = warpM * 32 + (lane & 15);
    const int aHalf = lane >> 4;
    const int bRow = warpN * 64 + ((lane >> 4) * 8) + (lane & 7);
    const int bHalf = (lane >> 3) & 1;

    // prologue: 2 stages in flight
    load_stage(0, 0); CP_COMMIT();
    load_stage(1, 1); CP_COMMIT();

    int buf = 0;
    for (int s = 0; s < NSTAGE; s++) {
        CP_WAIT1();          // stage s resident (s+1 may be in flight)
        __syncthreads();     // ring slot reuse safety
        if (s + 2 < NSTAGE) {
            int nbuf = buf + 2; if (nbuf >= 3) nbuf -= 3;
            load_stage(s + 2, nbuf);
            CP_COMMIT();
        }

        const uint32_t base = smem_base + (uint32_t)buf * STAGE_BYTES;
#pragma unroll
        for (int kk = 0; kk < 4; kk++) {
            uint32_t a[2][4], b[4][4];
#pragma unroll
            for (int mi = 0; mi < 2; mi++) {
                int r = aRow + mi * 16;
                int c16 = kk * 2 + aHalf;
                uint32_t off = (uint32_t)(r * 128 + ((c16 ^ (r & 7)) * 16));
                LDSM_X4(a[mi][0], a[mi][1], a[mi][2], a[mi][3], base + off);
            }
#pragma unroll
            for (int np = 0; np < 4; np++) {
                int r = bRow + np * 16;
                int c16 = kk * 2 + bHalf;
                uint32_t off = (uint32_t)(r * 128 + ((c16 ^ (r & 7)) * 16));
                LDSM_X4(b[np][0], b[np][1], b[np][2], b[np][3],
                        base + 16384u + off);
            }
#pragma unroll
            for (int mi = 0; mi < 2; mi++)
#pragma unroll
                for (int ni = 0; ni < 8; ni++) {
                    const int np = ni >> 1, sub = (ni & 1) * 2;
                    mma16816(acc[mi][ni], a[mi], b[np][sub], b[np][sub + 1]);
                }
        }
        if (++buf >= 3) buf = 0;
    }

    const int erow = rowBase + warpM * 32 + (lane >> 2);
    const int ecol0 = colBase + warpN * 64 + (lane & 3) * 2;
#pragma unroll
    for (int ni = 0; ni < 8; ni++) {
        const int col = ecol0 + ni * 8;
        const float sc = (col < qcols) ? QSCALE : 1.f;
        const float bx = bias[col], by = bias[col + 1];
#pragma unroll
        for (int mi = 0; mi < 2; mi++) {
            const int r0 = erow + mi * 16;
            float v0 = (acc[mi][ni][0] + bx) * sc;
            float v1 = (acc[mi][ni][1] + by) * sc;
            float v2 = (acc[mi][ni][2] + bx) * sc;
            float v3 = (acc[mi][ni][3] + by) * sc;
            if (Cf) {
                *(float2*)&Cf[(size_t)r0 * Ntot + col] = make_float2(v0, v1);
                *(float2*)&Cf[(size_t)(r0 + 8) * Ntot + col] = make_float2(v2, v3);
            } else {
                *(uint32_t*)&Ch[(size_t)r0 * Ntot + col] = pack_f16(v0, v1);
                *(uint32_t*)&Ch[(size_t)(r0 + 8) * Ntot + col] = pack_f16(v2, v3);
            }
        }
    }
}

// ---------------------------------------------------------------------------
// Flash attention on mma.sync fp16 (exp2-domain softmax).
// grid (S/128, B*H), 256 threads (8 warps x 16 q rows each).
// KV chunk = 64 rows; 3-buffer cp.async ring, ONE barrier per chunk.
// smem: Q 0 (16KB); ring at 16384, 3 x 16KB (K 0, V 8192 per buf). 64KB total
// -> multiple CTAs per SM.
// ---------------------------------------------------------------------------
#define FL_SMEM 65536
#define NCHUNK (S_LEN / 64)   // 32

__global__ __launch_bounds__(256, 1) void flash_mma_kernel(
    const __half* __restrict__ qkv, __half* __restrict__ oh)
{
    extern __shared__ char sm_raw[];
    const uint32_t sb = smem_u32(sm_raw);
    const int tid = threadIdx.x;
    const int wid = tid >> 5;
    const int lane = tid & 31;
    const int q0 = blockIdx.x * 128;
    const int b = blockIdx.y >> 4;
    const int h = blockIdx.y & 15;
    const int qcol = h * HDIM;
    const int kcol = EMBED + h * HDIM;
    const int vcol = 2 * EMBED + h * HDIM;

    // ---- load Q tile: 1024 cp16 (group 0) ----
#pragma unroll
    for (int i = 0; i < 4; i++) {
        int idx = tid + (i << 8);          // 0..1023
        int r = idx >> 3;
        int c16 = idx & 7;
        const void* src = qkv + (size_t)((q0 + r) * 2 + b) * QKV_COLS + qcol + c16 * 8;
        cp16(sb + (uint32_t)(r * 128 + ((c16 ^ (r & 7)) * 16)), src);
    }
    CP_COMMIT();

    auto load_kv = [&](int j0, int buf) {
        const uint32_t base = sb + 16384u + (uint32_t)buf * 16384u;
#pragma unroll
        for (int i = 0; i < 4; i++) {
            int idx = tid + (i << 8);       // 0..1023
            int mat = idx >> 9;             // 0:K 1:V
            int r = (idx >> 3) & 63;
            int c16 = idx & 7;
            int colb = mat ? vcol : kcol;
            const void* src = qkv + (size_t)((j0 + r) * 2 + b) * QKV_COLS + colb + c16 * 8;
            uint32_t dst = base + (uint32_t)(mat * 8192 + r * 128 +
                                             ((c16 ^ (r & 7)) * 16));
            cp16(dst, src);
        }
    };

    // prologue: kv chunks 0 and 1 in flight
    load_kv(0, 0);  CP_COMMIT();
    load_kv(64, 1); CP_COMMIT();

    CP_WAIT2();      // Q resident
    __syncthreads();

    // ---- Q fragments into registers ----
    uint32_t aq[4][4];
    {
        int r = wid * 16 + (lane & 15);
#pragma unroll
        for (int kk = 0; kk < 4; kk++) {
            int c16 = kk * 2 + (lane >> 4);
            uint32_t off = (uint32_t)(r * 128 + ((c16 ^ (r & 7)) * 16));
            LDSM_X4(aq[kk][0], aq[kk][1], aq[kk][2], aq[kk][3], sb + off);
        }
    }

    float O[8][4];
#pragma unroll
    for (int ni = 0; ni < 8; ni++)
#pragma unroll
        for (int j = 0; j < 4; j++) O[ni][j] = 0.f;
    float m0 = -1e30f, m1 = -1e30f, l0 = 0.f, l1 = 0.f;

    int buf = 0;
    for (int s = 0; s < NCHUNK; s++) {
        CP_WAIT1();          // chunk s resident
        __syncthreads();     // ring slot reuse safety
        if (s + 2 < NCHUNK) {
            int nbuf = buf + 2; if (nbuf >= 3) nbuf -= 3;
            load_kv((s + 2) * 64, nbuf);
            CP_COMMIT();
        }

        const uint32_t kb = sb + 16384u + (uint32_t)buf * 16384u;

        // ---- QK^T ----
        float sc[8][4];
#pragma unroll
        for (int ni = 0; ni < 8; ni++)
#pragma unroll
            for (int j = 0; j < 4; j++) sc[ni][j] = 0.f;

#pragma unroll
        for (int kk = 0; kk < 4; kk++) {
            uint32_t kf[4][4];
            int rb = ((lane >> 4) * 8) + (lane & 7);
            int c16 = kk * 2 + ((lane >> 3) & 1);
#pragma unroll
            for (int np = 0; np < 4; np++) {
                int r = rb + np * 16;
                uint32_t off = (uint32_t)(r * 128 + ((c16 ^ (r & 7)) * 16));
                LDSM_X4(kf[np][0], kf[np][1], kf[np][2], kf[np][3], kb + off);
            }
#pragma unroll
            for (int ni = 0; ni < 8; ni++) {
                const int np = ni >> 1, sub = (ni & 1) * 2;
                mma16816(sc[ni], aq[kk], kf[np][sub], kf[np][sub + 1]);
            }
        }

        // ---- online softmax (exp2 domain; two row-halves per thread) ----
#pragma unroll
        for (int hh = 0; hh < 2; hh++) {
            const int j0 = hh * 2, j1 = hh * 2 + 1;
            float& m = hh ? m1 : m0;
            float& l = hh ? l1 : l0;
            float mx = -1e30f;
#pragma unroll
            for (int ni = 0; ni < 8; ni++)
                mx = fmaxf(mx, fmaxf(sc[ni][j0], sc[ni][j1]));
            mx = fmaxf(mx, __shfl_xor_sync(0xffffffffu, mx, 1));
            mx = fmaxf(mx, __shfl_xor_sync(0xffffffffu, mx, 2));
            float mn = fmaxf(m, mx);
            float alpha = fast_exp2(m - mn);
            m = mn;
            float sum = 0.f;
#pragma unroll
            for (int ni = 0; ni < 8; ni++) {
                sc[ni][j0] = fast_exp2(sc[ni][j0] - mn);
                sc[ni][j1] = fast_exp2(sc[ni][j1] - mn);
                sum += sc[ni][j0] + sc[ni][j1];
            }
            sum += __shfl_xor_sync(0xffffffffu, sum, 1);
            sum += __shfl_xor_sync(0xffffffffu, sum, 2);
            l = l * alpha + sum;
#pragma unroll
            for (int ni = 0; ni < 8; ni++) {
                O[ni][j0] *= alpha;
                O[ni][j1] *= alpha;
            }
        }

        // ---- P @ V ----
#pragma unroll
        for (int kk2 = 0; kk2 < 4; kk2++) {
            uint32_t p[4];
            p[0] = pack_f16(sc[2 * kk2][0],     sc[2 * kk2][1]);
            p[1] = pack_f16(sc[2 * kk2][2],     sc[2 * kk2][3]);
            p[2] = pack_f16(sc[2 * kk2 + 1][0], sc[2 * kk2 + 1][1]);
            p[3] = pack_f16(sc[2 * kk2 + 1][2], sc[2 * kk2 + 1][3]);

            uint32_t vf[4][4];
            int g = lane >> 3;
            int row = kk2 * 16 + (g & 1) * 8 + (lane & 7);
#pragma unroll
            for (int g4 = 0; g4 < 4; g4++) {
                int c16 = g4 * 2 + (g >> 1);
                uint32_t off = (uint32_t)(row * 128 + ((c16 ^ (row & 7)) * 16));
                LDSM_X4_T(vf[g4][0], vf[g4][1], vf[g4][2], vf[g4][3],
                          kb + 8192u + off);
            }
#pragma unroll
            for (int ni = 0; ni < 8; ni++) {
                const int g4 = ni >> 1, sub = (ni & 1) * 2;
                mma16816(O[ni], p, vf[g4][sub], vf[g4][sub + 1]);
            }
        }
        if (++buf >= 3) buf = 0;
    }

    // ---- epilogue: normalize, convert fp16, store ----
    const float inv0 = 1.f / l0;
    const float inv1 = 1.f / l1;
    const int sA = q0 + wid * 16 + (lane >> 2);
    const size_t rowA = (size_t)(sA * 2 + b) * EMBED;
    const size_t rowB = (size_t)((sA + 8) * 2 + b) * EMBED;
    const int colb = h * HDIM + (lane & 3) * 2;
#pragma unroll
    for (int ni = 0; ni < 8; ni++) {
        const int col = colb + ni * 8;
        *(uint32_t*)&oh[rowA + col] = pack_f16(O[ni][0] * inv0, O[ni][1] * inv0);
        *(uint32_t*)&oh[rowB + col] = pack_f16(O[ni][2] * inv1, O[ni][3] * inv1);
    }
}

// ---------------------------------------------------------------------------
extern "C" void kernel_launch(void* const* d_in, const int* in_sizes, int n_in,
                              void* d_out, int out_size)
{
    (void)in_sizes; (void)n_in; (void)out_size;
    const float* x    = (const float*)d_in[0];
    const float* Win  = (const float*)d_in[1];
    const float* bin  = (const float*)d_in[2];
    const float* Wout = (const float*)d_in[3];
    const float* bout = (const float*)d_in[4];
    float* out = (float*)d_out;

    __half *xh, *w1h, *w2h, *qkvh, *ah;
    cudaGetSymbolAddress((void**)&xh, g_xh);
    cudaGetSymbolAddress((void**)&w1h, g_w1h);
    cudaGetSymbolAddress((void**)&w2h, g_w2h);
    cudaGetSymbolAddress((void**)&qkvh, g_qkvh);
    cudaGetSymbolAddress((void**)&ah, g_ah);

    cudaFuncSetAttribute(gemm_mma_kernel,
                         cudaFuncAttributeMaxDynamicSharedMemorySize, GEMM_SMEM);
    cudaFuncSetAttribute(flash_mma_kernel,
                         cudaFuncAttributeMaxDynamicSharedMemorySize, FL_SMEM);

    // 0) fp32 -> fp16 converts
    cvt_f16_kernel<<<(M_ROWS * EMBED) / 1024, 256>>>(
        (const float4*)x, (uint2*)xh);
    cvt_f16_kernel<<<(QKV_COLS * EMBED) / 1024, 256>>>(
        (const float4*)Win, (uint2*)w1h);
    cvt_f16_kernel<<<(EMBED * EMBED) / 1024, 256>>>(
        (const float4*)Wout, (uint2*)w2h);

    // 1) QKV projection -> fp16 qkv (Q pre-scaled by 0.125*log2e)
    gemm_mma_kernel<<<dim3(QKV_COLS / 256, M_ROWS / 128), 512, GEMM_SMEM>>>(
        xh, w1h, bin, nullptr, qkvh, QKV_COLS, EMBED);

    // 2) Flash attention on tensor cores -> fp16 attn
    flash_mma_kernel<<<dim3(S_LEN / 128, BATCH * HEADS), 256, FL_SMEM>>>(
        qkvh, ah);

    // 3) Output projection -> fp32 out
    gemm_mma_kernel<<<dim3(EMBED / 256, M_ROWS / 128), 512, GEMM_SMEM>>>(
        ah, w2h, bout, out, nullptr, EMBED, 0);
}

// round 9
// speedup vs baseline: 3.7411x; 1.1060x over previous
#include <cuda_runtime.h>
#include <cuda_fp16.h>
#include <cstdint>

// Problem constants
#define S_LEN 2048
#define BATCH 2
#define EMBED 1024
#define HEADS 16
#define HDIM  64
#define M_ROWS (S_LEN * BATCH)        // 4096
#define QKV_COLS (3 * EMBED)          // 3072

// Q scale folded with log2(e) so softmax can use exp2 directly
#define QSCALE 0.18033688011112042f   // 0.125 * log2(e)
#define ONES_H2 0x3C003C00u           // half2(1.0, 1.0)

// ---------------------------------------------------------------------------
// Scratch (device globals; no allocation in kernel_launch)
// ---------------------------------------------------------------------------
__device__ __align__(16) __half g_xh[(size_t)M_ROWS * EMBED];
__device__ __align__(16) __half g_w1h[(size_t)QKV_COLS * EMBED];
__device__ __align__(16) __half g_w2h[(size_t)EMBED * EMBED];
__device__ __align__(16) __half g_qkvh[(size_t)M_ROWS * QKV_COLS];
__device__ __align__(16) __half g_ah[(size_t)M_ROWS * EMBED];

// ---------------------------------------------------------------------------
// PTX helpers (baseline compute_103-safe: mma.sync + ldmatrix + cp.async)
// ---------------------------------------------------------------------------
__device__ __forceinline__ uint32_t smem_u32(const void* p) {
    uint32_t addr;
    asm("{ .reg .u64 t; cvta.to.shared.u64 t, %1; cvt.u32.u64 %0, t; }"
        : "=r"(addr) : "l"(p));
    return addr;
}

__device__ __forceinline__ void cp16(uint32_t dst, const void* src) {
    asm volatile("cp.async.cg.shared.global [%0], [%1], 16;" :: "r"(dst), "l"(src));
}
#define CP_COMMIT() asm volatile("cp.async.commit_group;" ::: "memory")
#define CP_WAIT1()  asm volatile("cp.async.wait_group 1;" ::: "memory")
#define CP_WAIT2()  asm volatile("cp.async.wait_group 2;" ::: "memory")

#define LDSM_X4(r0, r1, r2, r3, addr) \
    asm volatile("ldmatrix.sync.aligned.m8n8.x4.shared.b16 {%0,%1,%2,%3}, [%4];" \
        : "=r"(r0), "=r"(r1), "=r"(r2), "=r"(r3) : "r"(addr))

#define LDSM_X4_T(r0, r1, r2, r3, addr) \
    asm volatile("ldmatrix.sync.aligned.m8n8.x4.trans.shared.b16 {%0,%1,%2,%3}, [%4];" \
        : "=r"(r0), "=r"(r1), "=r"(r2), "=r"(r3) : "r"(addr))

__device__ __forceinline__ void mma16816(float* c, const uint32_t* a,
                                         const uint32_t b0, const uint32_t b1) {
    asm volatile(
        "mma.sync.aligned.m16n8k16.row.col.f32.f16.f16.f32 "
        "{%0,%1,%2,%3}, {%4,%5,%6,%7}, {%8,%9}, {%0,%1,%2,%3};"
        : "+f"(c[0]), "+f"(c[1]), "+f"(c[2]), "+f"(c[3])
        : "r"(a[0]), "r"(a[1]), "r"(a[2]), "r"(a[3]), "r"(b0), "r"(b1));
}

__device__ __forceinline__ float fast_exp2(float x) {
    float y;
    asm("ex2.approx.f32 %0, %1;" : "=f"(y) : "f"(x));
    return y;
}

__device__ __forceinline__ uint32_t pack_f16(float f0, float f1) {
    __half2 h = __floats2half2_rn(f0, f1);
    return *reinterpret_cast<uint32_t*>(&h);
}

// pack two fp32 and take exp2 in half2 (one cvt + one MUFU for 2 elements)
__device__ __forceinline__ uint32_t exp2_f16x2(float f0, float f1) {
    uint32_t h = pack_f16(f0, f1);
    uint32_t y;
    asm("ex2.approx.f16x2 %0, %1;" : "=r"(y) : "r"(h));
    return y;
}

// ---------------------------------------------------------------------------
// fp32 -> fp16 convert (vectorized by 4)
// ---------------------------------------------------------------------------
__global__ __launch_bounds__(256) void cvt_f16_kernel(
    const float4* __restrict__ in, uint2* __restrict__ out)
{
    int i = blockIdx.x * blockDim.x + threadIdx.x;
    float4 v = in[i];
    uint2 r;
    r.x = pack_f16(v.x, v.y);
    r.y = pack_f16(v.z, v.w);
    out[i] = r;
}

// ---------------------------------------------------------------------------
// mma.sync fp16 GEMM:  C[M,Ntot] = A[M,1024] * W[Ntot,1024]^T + bias
// CTA tile 128x256, 16 warps (4 M x 4 N), warp tile 32x64, 512 threads.
// K staged 64 elems; 3-buffer cp.async ring, ONE barrier per stage.
// grid = (Ntot/256, M/128).  Columns < qcols scaled by QSCALE.
// ---------------------------------------------------------------------------
#define GK 1024
#define KSTEP 64
#define NSTAGE (GK / KSTEP)          // 16
#define STAGE_BYTES 49152            // A 16KB + W 32KB
#define GEMM_SMEM (3 * STAGE_BYTES)  // 147456

__global__ __launch_bounds__(512, 1) void gemm_mma_kernel(
    const __half* __restrict__ A, const __half* __restrict__ W,
    const float* __restrict__ bias, float* __restrict__ Cf,
    __half* __restrict__ Ch, int Ntot, int qcols)
{
    extern __shared__ char sm_raw[];
    const uint32_t smem_base = smem_u32(sm_raw);
    const int tid = threadIdx.x;
    const int wid = tid >> 5;
    const int lane = tid & 31;
    const int warpM = wid & 3;          // 4 warps over M (32 rows each)
    const int warpN = wid >> 2;         // 4 warps over N (64 cols each)
    const int rowBase = blockIdx.y * 128;
    const int colBase = blockIdx.x * 256;

    auto load_stage = [&](int s, int buf) {
        const int k0 = s * KSTEP;
        const uint32_t base = smem_base + (uint32_t)buf * STAGE_BYTES;
#pragma unroll
        for (int i = 0; i < 6; i++) {
            int idx = tid + (i << 9);          // 0..3071
            if (idx < 1024) {
                int r = idx >> 3, c16 = idx & 7;
                const void* src = A + (size_t)(rowBase + r) * GK + k0 + c16 * 8;
                cp16(base + (uint32_t)(r * 128 + ((c16 ^ (r & 7)) * 16)), src);
            } else {
                int idx2 = idx - 1024;         // 0..2047
                int r = idx2 >> 3, c16 = idx2 & 7;
                const void* src = W + (size_t)(colBase + r) * GK + k0 + c16 * 8;
                cp16(base + 16384u + (uint32_t)(r * 128 + ((c16 ^ (r & 7)) * 16)),
                     src);
            }
        }
    };

    float acc[2][8][4];
#pragma unroll
    for (int mi = 0; mi < 2; mi++)
#pragma unroll
        for (int ni = 0; ni < 8; ni++)
#pragma unroll
            for (int j = 0; j < 4; j++) acc[mi][ni][j] = 0.f;

    const int aRow = warpM * 32 + (lane & 15);
    const int aHalf = lane >> 4;
    const int bRow = warpN * 64 + ((lane >> 4) * 8) + (lane & 7);
    const int bHalf = (lane >> 3) & 1;

    load_stage(0, 0); CP_COMMIT();
    load_stage(1, 1); CP_COMMIT();

    int buf = 0;
    for (int s = 0; s < NSTAGE; s++) {
        CP_WAIT1();
        __syncthreads();
        if (s + 2 < NSTAGE) {
            int nbuf = buf + 2; if (nbuf >= 3) nbuf -= 3;
            load_stage(s + 2, nbuf);
            CP_COMMIT();
        }

        const uint32_t base = smem_base + (uint32_t)buf * STAGE_BYTES;
#pragma unroll
        for (int kk = 0; kk < 4; kk++) {
            uint32_t a[2][4], b[4][4];
#pragma unroll
            for (int mi = 0; mi < 2; mi++) {
                int r = aRow + mi * 16;
                int c16 = kk * 2 + aHalf;
                uint32_t off = (uint32_t)(r * 128 + ((c16 ^ (r & 7)) * 16));
                LDSM_X4(a[mi][0], a[mi][1], a[mi][2], a[mi][3], base + off);
            }
#pragma unroll
            for (int np = 0; np < 4; np++) {
                int r = bRow + np * 16;
                int c16 = kk * 2 + bHalf;
                uint32_t off = (uint32_t)(r * 128 + ((c16 ^ (r & 7)) * 16));
                LDSM_X4(b[np][0], b[np][1], b[np][2], b[np][3],
                        base + 16384u + off);
            }
#pragma unroll
            for (int mi = 0; mi < 2; mi++)
#pragma unroll
                for (int ni = 0; ni < 8; ni++) {
                    const int np = ni >> 1, sub = (ni & 1) * 2;
                    mma16816(acc[mi][ni], a[mi], b[np][sub], b[np][sub + 1]);
                }
        }
        if (++buf >= 3) buf = 0;
    }

    const int erow = rowBase + warpM * 32 + (lane >> 2);
    const int ecol0 = colBase + warpN * 64 + (lane & 3) * 2;
#pragma unroll
    for (int ni = 0; ni < 8; ni++) {
        const int col = ecol0 + ni * 8;
        const float sc = (col < qcols) ? QSCALE : 1.f;
        const float bx = bias[col], by = bias[col + 1];
#pragma unroll
        for (int mi = 0; mi < 2; mi++) {
            const int r0 = erow + mi * 16;
            float v0 = (acc[mi][ni][0] + bx) * sc;
            float v1 = (acc[mi][ni][1] + by) * sc;
            float v2 = (acc[mi][ni][2] + bx) * sc;
            float v3 = (acc[mi][ni][3] + by) * sc;
            if (Cf) {
                *(float2*)&Cf[(size_t)r0 * Ntot + col] = make_float2(v0, v1);
                *(float2*)&Cf[(size_t)(r0 + 8) * Ntot + col] = make_float2(v2, v3);
            } else {
                *(uint32_t*)&Ch[(size_t)r0 * Ntot + col] = pack_f16(v0, v1);
                *(uint32_t*)&Ch[(size_t)(r0 + 8) * Ntot + col] = pack_f16(v2, v3);
            }
        }
    }
}

// ---------------------------------------------------------------------------
// Flash attention on mma.sync fp16, exp2 in f16x2, row-sums via ones-MMA.
// grid (S/128, B*H), 256 threads (8 warps x 16 q rows each).
// KV chunk = 64 rows; 3-buffer cp.async ring, ONE barrier per chunk.
// smem 64KB; __launch_bounds__(256,2) targets 2 CTAs/SM (<=128 regs).
// ---------------------------------------------------------------------------
#define FL_SMEM 65536
#define NCHUNK (S_LEN / 64)   // 32

__global__ __launch_bounds__(256, 2) void flash_mma_kernel(
    const __half* __restrict__ qkv, __half* __restrict__ oh)
{
    extern __shared__ char sm_raw[];
    const uint32_t sb = smem_u32(sm_raw);
    const int tid = threadIdx.x;
    const int wid = tid >> 5;
    const int lane = tid & 31;
    const int q0 = blockIdx.x * 128;
    const int b = blockIdx.y >> 4;
    const int h = blockIdx.y & 15;
    const int qcol = h * HDIM;
    const int kcol = EMBED + h * HDIM;
    const int vcol = 2 * EMBED + h * HDIM;

    // ---- load Q tile: 1024 cp16 (group 0) ----
#pragma unroll
    for (int i = 0; i < 4; i++) {
        int idx = tid + (i << 8);
        int r = idx >> 3;
        int c16 = idx & 7;
        const void* src = qkv + (size_t)((q0 + r) * 2 + b) * QKV_COLS + qcol + c16 * 8;
        cp16(sb + (uint32_t)(r * 128 + ((c16 ^ (r & 7)) * 16)), src);
    }
    CP_COMMIT();

    auto load_kv = [&](int j0, int buf) {
        const uint32_t base = sb + 16384u + (uint32_t)buf * 16384u;
#pragma unroll
        for (int i = 0; i < 4; i++) {
            int idx = tid + (i << 8);
            int mat = idx >> 9;             // 0:K 1:V
            int r = (idx >> 3) & 63;
            int c16 = idx & 7;
            int colb = mat ? vcol : kcol;
            const void* src = qkv + (size_t)((j0 + r) * 2 + b) * QKV_COLS + colb + c16 * 8;
            uint32_t dst = base + (uint32_t)(mat * 8192 + r * 128 +
                                             ((c16 ^ (r & 7)) * 16));
            cp16(dst, src);
        }
    };

    load_kv(0, 0);  CP_COMMIT();
    load_kv(64, 1); CP_COMMIT();

    CP_WAIT2();      // Q resident
    __syncthreads();

    // ---- Q fragments into registers ----
    uint32_t aq[4][4];
    {
        int r = wid * 16 + (lane & 15);
#pragma unroll
        for (int kk = 0; kk < 4; kk++) {
            int c16 = kk * 2 + (lane >> 4);
            uint32_t off = (uint32_t)(r * 128 + ((c16 ^ (r & 7)) * 16));
            LDSM_X4(aq[kk][0], aq[kk][1], aq[kk][2], aq[kk][3], sb + off);
        }
    }

    float O[8][4];
#pragma unroll
    for (int ni = 0; ni < 8; ni++)
#pragma unroll
        for (int j = 0; j < 4; j++) O[ni][j] = 0.f;
    float m0 = -1e30f, m1 = -1e30f, l0 = 0.f, l1 = 0.f;

    int buf = 0;
    for (int s = 0; s < NCHUNK; s++) {
        CP_WAIT1();
        __syncthreads();
        if (s + 2 < NCHUNK) {
            int nbuf = buf + 2; if (nbuf >= 3) nbuf -= 3;
            load_kv((s + 2) * 64, nbuf);
            CP_COMMIT();
        }

        const uint32_t kb = sb + 16384u + (uint32_t)buf * 16384u;

        // ---- QK^T ----
        float sc[8][4];
#pragma unroll
        for (int ni = 0; ni < 8; ni++)
#pragma unroll
            for (int j = 0; j < 4; j++) sc[ni][j] = 0.f;

#pragma unroll
        for (int kk = 0; kk < 4; kk++) {
            uint32_t kf[4][4];
            int rb = ((lane >> 4) * 8) + (lane & 7);
            int c16 = kk * 2 + ((lane >> 3) & 1);
#pragma unroll
            for (int np = 0; np < 4; np++) {
                int r = rb + np * 16;
                uint32_t off = (uint32_t)(r * 128 + ((c16 ^ (r & 7)) * 16));
                LDSM_X4(kf[np][0], kf[np][1], kf[np][2], kf[np][3], kb + off);
            }
#pragma unroll
            for (int ni = 0; ni < 8; ni++) {
                const int np = ni >> 1, sub = (ni & 1) * 2;
                mma16816(sc[ni], aq[kk], kf[np][sub], kf[np][sub + 1]);
            }
        }

        // ---- max/alpha bookkeeping (fp32) ----
        float mn0, mn1, alpha0, alpha1;
        {
            float mx = -1e30f;
#pragma unroll
            for (int ni = 0; ni < 8; ni++)
                mx = fmaxf(mx, fmaxf(sc[ni][0], sc[ni][1]));
            mx = fmaxf(mx, __shfl_xor_sync(0xffffffffu, mx, 1));
            mx = fmaxf(mx, __shfl_xor_sync(0xffffffffu, mx, 2));
            mn0 = fmaxf(m0, mx);
            alpha0 = fast_exp2(m0 - mn0);
            m0 = mn0;
        }
        {
            float mx = -1e30f;
#pragma unroll
            for (int ni = 0; ni < 8; ni++)
                mx = fmaxf(mx, fmaxf(sc[ni][2], sc[ni][3]));
            mx = fmaxf(mx, __shfl_xor_sync(0xffffffffu, mx, 1));
            mx = fmaxf(mx, __shfl_xor_sync(0xffffffffu, mx, 2));
            mn1 = fmaxf(m1, mx);
            alpha1 = fast_exp2(m1 - mn1);
            m1 = mn1;
        }
#pragma unroll
        for (int ni = 0; ni < 8; ni++) {
            O[ni][0] *= alpha0; O[ni][1] *= alpha0;
            O[ni][2] *= alpha1; O[ni][3] *= alpha1;
        }

        // ---- P (fp16 exp2) @ V, row sums via ones-MMA ----
        float sumacc[4] = {0.f, 0.f, 0.f, 0.f};
#pragma unroll
        for (int kk2 = 0; kk2 < 4; kk2++) {
            uint32_t p[4];
            p[0] = exp2_f16x2(sc[2 * kk2][0] - mn0,     sc[2 * kk2][1] - mn0);
            p[1] = exp2_f16x2(sc[2 * kk2][2] - mn1,     sc[2 * kk2][3] - mn1);
            p[2] = exp2_f16x2(sc[2 * kk2 + 1][0] - mn0, sc[2 * kk2 + 1][1] - mn0);
            p[3] = exp2_f16x2(sc[2 * kk2 + 1][2] - mn1, sc[2 * kk2 + 1][3] - mn1);

            // row sums: B = all ones -> every c column = sum_k P[r][k]
            mma16816(sumacc, p, ONES_H2, ONES_H2);

            uint32_t vf[4][4];
            int g = lane >> 3;
            int row = kk2 * 16 + (g & 1) * 8 + (lane & 7);
#pragma unroll
            for (int g4 = 0; g4 < 4; g4++) {
                int c16 = g4 * 2 + (g >> 1);
                uint32_t off = (uint32_t)(row * 128 + ((c16 ^ (row & 7)) * 16));
                LDSM_X4_T(vf[g4][0], vf[g4][1], vf[g4][2], vf[g4][3],
                          kb + 8192u + off);
            }
#pragma unroll
            for (int ni = 0; ni < 8; ni++) {
                const int g4 = ni >> 1, sub = (ni & 1) * 2;
                mma16816(O[ni], p, vf[g4][sub], vf[g4][sub + 1]);
            }
        }
        l0 = l0 * alpha0 + sumacc[0];
        l1 = l1 * alpha1 + sumacc[2];

        if (++buf >= 3) buf = 0;
    }

    // ---- epilogue: normalize, convert fp16, store ----
    const float inv0 = 1.f / l0;
    const float inv1 = 1.f / l1;
    const int sA = q0 + wid * 16 + (lane >> 2);
    const size_t rowA = (size_t)(sA * 2 + b) * EMBED;
    const size_t rowB = (size_t)((sA + 8) * 2 + b) * EMBED;
    const int colb = h * HDIM + (lane & 3) * 2;
#pragma unroll
    for (int ni = 0; ni < 8; ni++) {
        const int col = colb + ni * 8;
        *(uint32_t*)&oh[rowA + col] = pack_f16(O[ni][0] * inv0, O[ni][1] * inv0);
        *(uint32_t*)&oh[rowB + col] = pack_f16(O[ni][2] * inv1, O[ni][3] * inv1);
    }
}

// ---------------------------------------------------------------------------
extern "C" void kernel_launch(void* const* d_in, const int* in_sizes, int n_in,
                              void* d_out, int out_size)
{
    (void)in_sizes; (void)n_in; (void)out_size;
    const float* x    = (const float*)d_in[0];
    const float* Win  = (const float*)d_in[1];
    const float* bin  = (const float*)d_in[2];
    const float* Wout = (const float*)d_in[3];
    const float* bout = (const float*)d_in[4];
    float* out = (float*)d_out;

    __half *xh, *w1h, *w2h, *qkvh, *ah;
    cudaGetSymbolAddress((void**)&xh, g_xh);
    cudaGetSymbolAddress((void**)&w1h, g_w1h);
    cudaGetSymbolAddress((void**)&w2h, g_w2h);
    cudaGetSymbolAddress((void**)&qkvh, g_qkvh);
    cudaGetSymbolAddress((void**)&ah, g_ah);

    cudaFuncSetAttribute(gemm_mma_kernel,
                         cudaFuncAttributeMaxDynamicSharedMemorySize, GEMM_SMEM);
    cudaFuncSetAttribute(flash_mma_kernel,
                         cudaFuncAttributeMaxDynamicSharedMemorySize, FL_SMEM);

    // 0) fp32 -> fp16 converts
    cvt_f16_kernel<<<(M_ROWS * EMBED) / 1024, 256>>>(
        (const float4*)x, (uint2*)xh);
    cvt_f16_kernel<<<(QKV_COLS * EMBED) / 1024, 256>>>(
        (const float4*)Win, (uint2*)w1h);
    cvt_f16_kernel<<<(EMBED * EMBED) / 1024, 256>>>(
        (const float4*)Wout, (uint2*)w2h);

    // 1) QKV projection -> fp16 qkv (Q pre-scaled by 0.125*log2e)
    gemm_mma_kernel<<<dim3(QKV_COLS / 256, M_ROWS / 128), 512, GEMM_SMEM>>>(
        xh, w1h, bin, nullptr, qkvh, QKV_COLS, EMBED);

    // 2) Flash attention on tensor cores -> fp16 attn
    flash_mma_kernel<<<dim3(S_LEN / 128, BATCH * HEADS), 256, FL_SMEM>>>(
        qkvh, ah);

    // 3) Output projection -> fp32 out
    gemm_mma_kernel<<<dim3(EMBED / 256, M_ROWS / 128), 512, GEMM_SMEM>>>(
        ah, w2h, bout, out, nullptr, EMBED, 0);
}